// round 12
// baseline (speedup 1.0000x reference)
#include <cuda_runtime.h>
#include <cuda_bf16.h>
#include <cuda_fp16.h>
#include <math.h>

// ---------------- problem constants ----------------
#define BATCH     16
#define SEQLEN    512
#define DMODEL    1024
#define DSTATE    128
#define DCONV     4
#define HEADDIM   64
#define DSSM      2048
#define NHEADS    32
#define CONVDIM   2304            // DSSM + 2*DSTATE
#define DINPROJ   4384            // 2*DSSM + 2*DSTATE + NHEADS
#define ACTDIM    2336            // CONVDIM + NHEADS
#define NCTA      128
#define NTHR      512
#define EPSV      1e-5f
#define WSCALE    64.0f
#define WSCALE_INV (1.0f / 64.0f)

// scan SMEM layout (floats)
#define SM_STATE  0                        // 256*132 = 33792 (state[p][n], pad 132)
#define SM_Y      33792                    // 16*512 = 8192 (warp partials / scratch)
#define SM_BC     (33792 + 8192)           // 1024
#define SM_RED    (33792 + 8192 + 1024)    // 32
#define SM_TOTALF (33792 + 8192 + 1024 + 32)

// ---------------- device scratch ----------------
__device__ float g_zxbcdt[BATCH * SEQLEN * DINPROJ];
__device__ float g_xbcconv[BATCH * SEQLEN * CONVDIM];
__device__ float g_act[BATCH * ACTDIM];
__device__ float g_mspart[BATCH * 32];          // per (batch, head) sum of g^2
__device__ unsigned g_arrive[NCTA * 32];        // padded per-CTA epoch flags (monotonic)
__device__ unsigned g_release;                  // epoch base carrier across replays
// W fragments (fp16 single plane): [cta][s(128)][lane(32)][nt(4)][b0,b1] u32 -> 16.8 MB
__device__ unsigned g_wfrag[128 * 128 * 256];
// Y fragments (fp16 hi/lo): [hilo][s(128)][lane(32)][reg(4)] u32 (half2) -> 128 KB
__device__ unsigned g_yfrag[2 * 128 * 32 * 4];

// ---------------- helpers ----------------
__device__ __forceinline__ float silu_f(float v) { return v / (1.0f + expf(-v)); }
__device__ __forceinline__ float softplus_f(float v) { return (v > 20.0f) ? v : log1pf(expf(v)); }

__device__ __forceinline__ void upk2(unsigned long long v, float& lo, float& hi) {
    unsigned a, b;
    asm("mov.b64 {%0, %1}, %2;" : "=r"(a), "=r"(b) : "l"(v));
    lo = __uint_as_float(a); hi = __uint_as_float(b);
}
__device__ __forceinline__ unsigned long long pk2(float lo, float hi) {
    unsigned long long r;
    asm("mov.b64 %0, {%1, %2};" : "=l"(r) : "r"(__float_as_uint(lo)), "r"(__float_as_uint(hi)));
    return r;
}
__device__ __forceinline__ unsigned long long fma2(unsigned long long a, unsigned long long b,
                                                   unsigned long long c) {
    unsigned long long d;
    asm("fma.rn.f32x2 %0, %1, %2, %3;" : "=l"(d) : "l"(a), "l"(b), "l"(c));
    return d;
}
__device__ __forceinline__ unsigned long long mul2(unsigned long long a, unsigned long long b) {
    unsigned long long d;
    asm("mul.rn.f32x2 %0, %1, %2;" : "=l"(d) : "l"(a), "l"(b));
    return d;
}
__device__ __forceinline__ unsigned tf32_of(float x) {
    unsigned r;
    asm("cvt.rna.tf32.f32 %0, %1;" : "=r"(r) : "f"(x));
    return r;
}

// ---- strong (L2-coherent) memory ops ----
__device__ __forceinline__ void st_release_u(unsigned* p, unsigned v) {
    asm volatile("st.release.gpu.global.u32 [%0], %1;" :: "l"(p), "r"(v) : "memory");
}
__device__ __forceinline__ unsigned ld_acquire_u(const unsigned* p) {
    unsigned v;
    asm volatile("ld.acquire.gpu.global.u32 %0, [%1];" : "=r"(v) : "l"(p) : "memory");
    return v;
}
__device__ __forceinline__ float ld_rlx_f(const float* p) {
    float v;
    asm volatile("ld.relaxed.gpu.global.f32 %0, [%1];" : "=f"(v) : "l"(p) : "memory");
    return v;
}
__device__ __forceinline__ void st_rlx_f(float* p, float v) {
    asm volatile("st.relaxed.gpu.global.f32 [%0], %1;" :: "l"(p), "f"(v) : "memory");
}
__device__ __forceinline__ void st_rlx_u(unsigned* p, unsigned v) {
    asm volatile("st.relaxed.gpu.global.u32 [%0], %1;" :: "l"(p), "r"(v) : "memory");
}
__device__ __forceinline__ void st_rlx_b16(unsigned short* p, unsigned short v) {
    asm volatile("st.relaxed.gpu.global.b16 [%0], %1;" :: "l"(p), "h"(v) : "memory");
}
__device__ __forceinline__ float2 ld_rlx_f2(const float* p) {
    float2 v;
    asm volatile("ld.relaxed.gpu.global.v2.f32 {%0,%1}, [%2];"
                 : "=f"(v.x), "=f"(v.y) : "l"(p) : "memory");
    return v;
}
__device__ __forceinline__ float4 ld_rlx_f4(const float* p) {
    float4 v;
    asm volatile("ld.relaxed.gpu.global.v4.f32 {%0,%1,%2,%3}, [%4];"
                 : "=f"(v.x), "=f"(v.y), "=f"(v.z), "=f"(v.w) : "l"(p) : "memory");
    return v;
}

union F4U { float4 f; unsigned long long u[2]; unsigned v[4]; };

// FLAT single-hop grid barrier: every CTA's first 128 threads poll all flags.
__device__ __forceinline__ void grid_barrier(int cta, unsigned epoch) {
    __syncthreads();
    if (threadIdx.x == 0) st_release_u(&g_arrive[cta * 32], epoch);
    if (threadIdx.x < 128) {
        while (ld_acquire_u(&g_arrive[threadIdx.x * 32]) < epoch) { }
    }
    __syncthreads();
}

// fp16 MMA: D[16x8] += A[16x16] * B[16x8]  (non-volatile: let ptxas schedule)
__device__ __forceinline__ void mma_f16(float* d, const unsigned* a, unsigned b0, unsigned b1) {
    asm("mma.sync.aligned.m16n8k16.row.col.f32.f16.f16.f32 "
        "{%0,%1,%2,%3}, {%4,%5,%6,%7}, {%8,%9}, {%0,%1,%2,%3};"
        : "+f"(d[0]), "+f"(d[1]), "+f"(d[2]), "+f"(d[3])
        : "r"(a[0]), "r"(a[1]), "r"(a[2]), "r"(a[3]), "r"(b0), "r"(b1));
}

// ---------------- kernel 0: precompute W fragments (fp16, scaled) ----------------
__global__ __launch_bounds__(256) void wfrag_kernel(const float* __restrict__ W_rxbc,
                                                    const float* __restrict__ W_rdt,
                                                    const float* __restrict__ W_out) {
    int idx = blockIdx.x * 256 + threadIdx.x;      // < 128*128*32*4
    int nt   = idx & 3;
    int lane = (idx >> 2) & 31;
    int s    = (idx >> 7) & 127;
    int cta  = idx >> 14;
    int hasdt = (cta < NHEADS) ? 1 : 0;
    int ntask = 18 + hasdt + 8;
    int n_local = nt * 8 + (lane >> 2);
    int k0 = s * 16 + (lane & 3) * 2;

    float w00 = 0.f, w01 = 0.f, w10 = 0.f, w11 = 0.f;
    float sc = 1.0f;
    if (n_local < ntask) {
        const float* p;
        if (n_local < 18) { p = W_rxbc + (size_t)(cta * 18 + n_local) * DSSM; sc = WSCALE; }
        else if (hasdt && n_local == 18) { p = W_rdt + (size_t)cta * DSSM; sc = WSCALE; }
        else p = W_out + (size_t)(cta * 8 + n_local - 18 - hasdt) * DSSM;
        w00 = p[k0]; w01 = p[k0 + 1]; w10 = p[k0 + 8]; w11 = p[k0 + 9];
    }

    unsigned short h00 = __half_as_ushort(__float2half_rn(w00 * sc));
    unsigned short h01 = __half_as_ushort(__float2half_rn(w01 * sc));
    unsigned short h10 = __half_as_ushort(__float2half_rn(w10 * sc));
    unsigned short h11 = __half_as_ushort(__float2half_rn(w11 * sc));

    size_t base = (size_t)(cta * 128 + s) * 256 + lane * 8 + nt * 2;
    g_wfrag[base]     = (unsigned)h00 | ((unsigned)h01 << 16);
    g_wfrag[base + 1] = (unsigned)h10 | ((unsigned)h11 << 16);
}

// ---------------- kernel 1: in_proj GEMM, tf32 mma (unchanged) --------
#define ASTR 36
#define IP_AH 0
#define IP_AL (2 * 128 * ASTR)
#define IP_BH (4 * 128 * ASTR)
#define IP_BL (4 * 128 * ASTR + 2 * 64 * ASTR)
#define IP_TOTALF (4 * 128 * ASTR + 4 * 64 * ASTR)

__device__ __forceinline__ void mma_tf32(float* d, const unsigned* a, const unsigned* b) {
    asm volatile(
        "mma.sync.aligned.m16n8k8.row.col.f32.tf32.tf32.f32 "
        "{%0,%1,%2,%3}, {%4,%5,%6,%7}, {%8,%9}, {%0,%1,%2,%3};"
        : "+f"(d[0]), "+f"(d[1]), "+f"(d[2]), "+f"(d[3])
        : "r"(a[0]), "r"(a[1]), "r"(a[2]), "r"(a[3]), "r"(b[0]), "r"(b[1]));
}

__global__ __launch_bounds__(256) void inproj_kernel(const float* __restrict__ U,
                                                     const float* __restrict__ Win) {
    extern __shared__ float smf[];
    const int N = DINPROJ;
    const int K = DMODEL;

    const int tid  = threadIdx.x;
    const int lane = tid & 31;
    const int warp = tid >> 5;
    const int mbase = blockIdx.y * 128;
    const int nbase = blockIdx.x * 64;
    const int mrow0 = (warp & 3) * 32;
    const int ncol0 = (warp >> 2) * 32;

    const int arow = tid >> 1;
    const int acb  = (tid & 1) * 16;
    const int brow = tid >> 2;
    const int bcb  = (tid & 3) * 8;

    float C[2][4][4];
#pragma unroll
    for (int mt = 0; mt < 2; mt++)
#pragma unroll
        for (int nt = 0; nt < 4; nt++)
#pragma unroll
            for (int e = 0; e < 4; e++) C[mt][nt][e] = 0.0f;

    float4 aReg[4];
    float4 bReg[2];

    auto ldg_chunk = [&](int k0) {
#pragma unroll
        for (int q = 0; q < 4; q++)
            aReg[q] = *(const float4*)(U + (mbase + arow) * K + k0 + acb + q * 4);
        if (nbase + brow < N) {
#pragma unroll
            for (int q = 0; q < 2; q++)
                bReg[q] = *(const float4*)(Win + (nbase + brow) * K + k0 + bcb + q * 4);
        } else {
            bReg[0] = make_float4(0.f, 0.f, 0.f, 0.f);
            bReg[1] = make_float4(0.f, 0.f, 0.f, 0.f);
        }
    };

    auto sts_chunk = [&](int buf) {
        float* Ah = smf + IP_AH + buf * 128 * ASTR;
        float* Al = smf + IP_AL + buf * 128 * ASTR;
        float* Bh = smf + IP_BH + buf * 64 * ASTR;
        float* Bl = smf + IP_BL + buf * 64 * ASTR;
#pragma unroll
        for (int q = 0; q < 4; q++) {
            const float* v = (const float*)&aReg[q];
#pragma unroll
            for (int e = 0; e < 4; e++) {
                float x = v[e];
                unsigned hb = tf32_of(x);
                float hf = __uint_as_float(hb);
                unsigned lb = tf32_of(x - hf);
                Ah[arow * ASTR + acb + q * 4 + e] = hf;
                Al[arow * ASTR + acb + q * 4 + e] = __uint_as_float(lb);
            }
        }
#pragma unroll
        for (int q = 0; q < 2; q++) {
            const float* v = (const float*)&bReg[q];
#pragma unroll
            for (int e = 0; e < 4; e++) {
                float x = v[e];
                unsigned hb = tf32_of(x);
                float hf = __uint_as_float(hb);
                unsigned lb = tf32_of(x - hf);
                Bh[brow * ASTR + bcb + q * 4 + e] = hf;
                Bl[brow * ASTR + bcb + q * 4 + e] = __uint_as_float(lb);
            }
        }
    };

    ldg_chunk(0);
    sts_chunk(0);
    __syncthreads();

    const int NCHUNK = K / 32;
    for (int c = 0; c < NCHUNK; c++) {
        int buf = c & 1;
        if (c + 1 < NCHUNK) ldg_chunk((c + 1) * 32);

        const unsigned* Ah = (const unsigned*)(smf + IP_AH + buf * 128 * ASTR);
        const unsigned* Al = (const unsigned*)(smf + IP_AL + buf * 128 * ASTR);
        const unsigned* Bh = (const unsigned*)(smf + IP_BH + buf * 64 * ASTR);
        const unsigned* Bl = (const unsigned*)(smf + IP_BL + buf * 64 * ASTR);

#pragma unroll
        for (int ks = 0; ks < 4; ks++) {
            int kc = ks * 8;
            unsigned ah[2][4], al[2][4], bh[4][2], bl[4][2];
#pragma unroll
            for (int mt = 0; mt < 2; mt++) {
                int r0 = mrow0 + mt * 16 + (lane >> 2);
                int cc = kc + (lane & 3);
                ah[mt][0] = Ah[r0 * ASTR + cc];
                ah[mt][1] = Ah[(r0 + 8) * ASTR + cc];
                ah[mt][2] = Ah[r0 * ASTR + cc + 4];
                ah[mt][3] = Ah[(r0 + 8) * ASTR + cc + 4];
                al[mt][0] = Al[r0 * ASTR + cc];
                al[mt][1] = Al[(r0 + 8) * ASTR + cc];
                al[mt][2] = Al[r0 * ASTR + cc + 4];
                al[mt][3] = Al[(r0 + 8) * ASTR + cc + 4];
            }
#pragma unroll
            for (int nt = 0; nt < 4; nt++) {
                int n0 = ncol0 + nt * 8 + (lane >> 2);
                int kk = kc + (lane & 3);
                bh[nt][0] = Bh[n0 * ASTR + kk];
                bh[nt][1] = Bh[n0 * ASTR + kk + 4];
                bl[nt][0] = Bl[n0 * ASTR + kk];
                bl[nt][1] = Bl[n0 * ASTR + kk + 4];
            }
#pragma unroll
            for (int mt = 0; mt < 2; mt++)
#pragma unroll
                for (int nt = 0; nt < 4; nt++) {
                    mma_tf32(C[mt][nt], ah[mt], bh[nt]);
                    mma_tf32(C[mt][nt], al[mt], bh[nt]);
                    mma_tf32(C[mt][nt], ah[mt], bl[nt]);
                }
        }

        __syncthreads();
        if (c + 1 < NCHUNK) {
            sts_chunk(buf ^ 1);
            __syncthreads();
        }
    }

#pragma unroll
    for (int mt = 0; mt < 2; mt++) {
        int row = mbase + mrow0 + mt * 16 + (lane >> 2);
#pragma unroll
        for (int nt = 0; nt < 4; nt++) {
            int col = nbase + ncol0 + nt * 8 + (lane & 3) * 2;
            if (col < N) {
                g_zxbcdt[row * N + col]           = C[mt][nt][0];
                g_zxbcdt[row * N + col + 1]       = C[mt][nt][1];
                g_zxbcdt[(row + 8) * N + col]     = C[mt][nt][2];
                g_zxbcdt[(row + 8) * N + col + 1] = C[mt][nt][3];
            }
        }
    }
}

// ---------------- kernel 2: causal depthwise conv ----------------
__global__ __launch_bounds__(256) void conv_kernel(const float* __restrict__ conv_w,
                                                   const float* __restrict__ conv_b) {
    int idx = blockIdx.x * blockDim.x + threadIdx.x;
    if (idx >= BATCH * SEQLEN * CONVDIM) return;
    int c  = idx % CONVDIM;
    int bt = idx / CONVDIM;
    int t  = bt % SEQLEN;
    int b  = bt / SEQLEN;
    float accv = conv_b[c];
#pragma unroll
    for (int k = 0; k < DCONV; k++) {
        int tt = t + k - (DCONV - 1);
        if (tt >= 0)
            accv = fmaf(g_zxbcdt[(b * SEQLEN + tt) * DINPROJ + DSSM + c],
                        conv_w[c * DCONV + k], accv);
    }
    g_xbcconv[idx] = accv;
}

// ---------------- kernel 3: persistent scan, fp16 single-plane W ----------------
__global__ __launch_bounds__(NTHR, 1) void scan_kernel(
    const float* __restrict__ dt_bias, const float* __restrict__ A_log,
    const float* __restrict__ D_param, const float* __restrict__ norm_w,
    float* __restrict__ out) {

    extern __shared__ float sm[];
    float* s_state = sm + SM_STATE;       // state[p][n], p = b_loc*64+dd, stride 132
    float* s_y     = sm + SM_Y;           // 16 warps x 512 partials / phase-B scratch
    float* s_bc    = sm + SM_BC;
    float* s_red   = sm + SM_RED;
    __shared__ unsigned s_base;

    const int tid  = threadIdx.x;
    const int cta  = blockIdx.x;
    const int lane = tid & 31;
    const int warp = tid >> 5;

    if (tid == 0) s_base = ld_acquire_u(&g_release);
    {
        int i = cta * NTHR + tid;
        if (i < 2 * 128 * 32 * 4) st_rlx_u(&g_yfrag[i], 0u);
    }
    for (int i = tid; i < 256 * 132; i += NTHR) s_state[i] = 0.0f;
    __syncthreads();
    unsigned epoch = s_base + 1;

    const int hasdt = (cta < NHEADS) ? 1 : 0;
    const int ntask = 18 + hasdt + 8;

    // ---- phase B mapping: p = tid & 255, half = tid >> 8 ----
    const int p     = tid & 255;
    const int half  = tid >> 8;
    const int h  = cta & 31;
    const int bg = cta >> 5;
    const int b_loc = p >> 6;
    const int dd    = p & 63;
    const int bglb  = bg * 4 + b_loc;
    const float Ah  = -expf(A_log[h]);
    const float dtb = dt_bias[h];
    const float Dh  = D_param[h];
    const float nw  = norm_w[h * HEADDIM + dd];
    const int n0    = half * 64;

    // Y-frag slot (based on p; only half==0 writes)
    int yk = h * HEADDIM + dd;
    int ys = yk >> 4;
    int yc = yk & 15;
    int yreg = ((yc >= 8) ? 2 : 0) + ((bglb >= 8) ? 1 : 0);
    int yln  = ((bglb & 7) << 2) | ((yc >> 1) & 3);
    int yhalf = yc & 1;
    unsigned short* yb16 = (unsigned short*)g_yfrag;
    int ywi = ((ys * 32 + yln) * 4 + yreg) * 2 + yhalf;

    // rsqrt loader mapping (tid < 128): batch rb = tid>>3, quarter rq = tid&7
    const int rb = tid >> 3;
    const int rq = tid & 7;

    grid_barrier(cta, epoch++);

    for (int t = 0; t <= SEQLEN; t++) {
        // =================== phase A: D[16,32] = Y @ W^T, pipelined ===========
        if (tid < 128) {
            float4 v = ld_rlx_f4(g_mspart + rb * 32 + rq * 4);
            float s = (v.x + v.y) + (v.z + v.w);
            s += __shfl_xor_sync(0xffffffffu, s, 1);
            s += __shfl_xor_sync(0xffffffffu, s, 2);
            s += __shfl_xor_sync(0xffffffffu, s, 4);
            if (rq == 0) s_red[rb] = rsqrtf(s * (1.0f / (float)DSSM) + EPSV);
        }

        float acc[4][4];
#pragma unroll
        for (int nt = 0; nt < 4; nt++)
#pragma unroll
            for (int e = 0; e < 4; e++) acc[nt][e] = 0.0f;

        uint4 wb[2][2];
        F4U yhb[2], ylb[2];
        auto load_slice = [&](int buf, int sl) {
            int s = (warp << 3) + sl;
            const uint4* wp = (const uint4*)(g_wfrag + (size_t)(cta * 128 + s) * 256 + lane * 8);
            yhb[buf].f = ld_rlx_f4((const float*)(g_yfrag + (s * 32 + lane) * 4));
            ylb[buf].f = ld_rlx_f4((const float*)(g_yfrag + 16384 + (s * 32 + lane) * 4));
            wb[buf][0] = wp[0];
            wb[buf][1] = wp[1];
        };

        load_slice(0, 0);
#pragma unroll
        for (int sl = 0; sl < 8; sl++) {
            int cb = sl & 1;
            if (sl < 7) load_slice(cb ^ 1, sl + 1);    // prefetch next slice first

            mma_f16(acc[0], yhb[cb].v, wb[cb][0].x, wb[cb][0].y);
            mma_f16(acc[0], ylb[cb].v, wb[cb][0].x, wb[cb][0].y);

            mma_f16(acc[1], yhb[cb].v, wb[cb][0].z, wb[cb][0].w);
            mma_f16(acc[1], ylb[cb].v, wb[cb][0].z, wb[cb][0].w);

            mma_f16(acc[2], yhb[cb].v, wb[cb][1].x, wb[cb][1].y);
            mma_f16(acc[2], ylb[cb].v, wb[cb][1].x, wb[cb][1].y);

            mma_f16(acc[3], yhb[cb].v, wb[cb][1].z, wb[cb][1].w);
            mma_f16(acc[3], ylb[cb].v, wb[cb][1].z, wb[cb][1].w);
        }

        {
            int bq = lane >> 2;
            int c2 = (lane & 3) * 2;
            float* wp = s_y + warp * 512;
#pragma unroll
            for (int nt = 0; nt < 4; nt++) {
                *(float2*)(wp + bq * 32 + nt * 8 + c2)       = make_float2(acc[nt][0], acc[nt][1]);
                *(float2*)(wp + (bq + 8) * 32 + nt * 8 + c2) = make_float2(acc[nt][2], acc[nt][3]);
            }
        }
        __syncthreads();

        // reduce 16 warp planes; one group per thread
        {
            int g = tid;
            int b = g >> 5;
            int r = g & 31;
            if (r < ntask) {
                float sum = 0.0f;
#pragma unroll
                for (int w = 0; w < 16; w++) sum += s_y[w * 512 + g];
                float val = sum * s_red[b];
                if (r < 18 + hasdt) val *= WSCALE_INV;   // un-scale rxbc/dt rows
                if (r < 18) {
                    if (t < SEQLEN) {
                        int idxv = cta * 18 + r;
                        float base = g_xbcconv[(b * SEQLEN + t) * CONVDIM + idxv];
                        st_rlx_f(&g_act[b * ACTDIM + idxv], silu_f(base + val));
                    }
                } else if (hasdt && r == 18) {
                    if (t < SEQLEN) {
                        float base = g_zxbcdt[(b * SEQLEN + t) * DINPROJ + (DSSM + CONVDIM) + cta];
                        st_rlx_f(&g_act[b * ACTDIM + CONVDIM + cta], silu_f(base + val));
                    }
                } else {
                    int idxv = cta * 8 + (r - 18 - hasdt);
                    if (t >= 1) out[(b * SEQLEN + (t - 1)) * DMODEL + idxv] = val;
                }
            }
        }

        if (t == SEQLEN) break;

        grid_barrier(cta, epoch++);   // act(t) visible

        // =================== phase B (n-range split across halves) ===================
        float x   = ld_rlx_f(&g_act[bglb * ACTDIM + h * HEADDIM + dd]);
        float dtr = ld_rlx_f(&g_act[bglb * ACTDIM + CONVDIM + h]);
        float z   = g_zxbcdt[(bglb * SEQLEN + t) * DINPROJ + h * HEADDIM + dd];

        {
            int i = tid * 2;           // 512 threads x float2 = 1024 floats
            int bl = i >> 8, k = i & 255;
            float2 v = ld_rlx_f2((const float*)&g_act[(bg * 4 + bl) * ACTDIM + DSSM + k]);
            *(float2*)(s_bc + i) = v;
        }
        __syncthreads();

        float g;
        {
            float dt_v = softplus_f(dtr + dtb);
            float dA  = expf(dt_v * Ah);
            float coef = dt_v * x;

            unsigned long long dA2 = pk2(dA, dA);
            unsigned long long cf2 = pk2(coef, coef);
            unsigned long long acc2 = 0ULL;

            const float* bvp = s_bc + b_loc * 256 + n0;
            const float* cvp = s_bc + b_loc * 256 + 128 + n0;
            float* sp = s_state + p * 132 + n0;
#pragma unroll 4
            for (int n = 0; n < 64; n += 4) {
                F4U sv, bv, cv;
                sv.f = *(float4*)(sp + n);
                bv.f = *(const float4*)(bvp + n);
                cv.f = *(const float4*)(cvp + n);
                sv.u[0] = fma2(sv.u[0], dA2, mul2(cf2, bv.u[0]));
                sv.u[1] = fma2(sv.u[1], dA2, mul2(cf2, bv.u[1]));
                acc2 = fma2(sv.u[0], cv.u[0], acc2);
                acc2 = fma2(sv.u[1], cv.u[1], acc2);
                *(float4*)(sp + n) = sv.f;
            }
            float alo, ahi;
            upk2(acc2, alo, ahi);
            s_y[tid] = alo + ahi;     // partial dot over this half's n-range
        }
        __syncthreads();

        if (half == 0) {
            float accv = s_y[tid] + s_y[tid + 256];
            float y = fmaf(Dh, x, accv);
            g = y * silu_f(z);

            // write Y fragment (fp16 hi/lo) for phase A(t+1)
            float yv = g * nw;
            __half hb = __float2half_rn(yv);
            float hf = __half2float(hb);
            __half lb = __float2half_rn(yv - hf);
            st_rlx_b16(yb16 + ywi, __half_as_ushort(hb));
            st_rlx_b16(yb16 + 32768 + ywi, __half_as_ushort(lb));

            float gsq = g * g;
#pragma unroll
            for (int off = 16; off > 0; off >>= 1)
                gsq += __shfl_xor_sync(0xffffffffu, gsq, off);
            if (lane == 0) s_red[16 + warp] = gsq;   // warps 0..7
        }
        __syncthreads();

        if (tid < 4) {
            float part = s_red[16 + 2 * tid] + s_red[16 + 2 * tid + 1];
            st_rlx_f(&g_mspart[(bg * 4 + tid) * 32 + h], part);
        }

        grid_barrier(cta, epoch++);   // yfrags + partials visible
    }
}

// ---------------- launcher ----------------
extern "C" void kernel_launch(void* const* d_in, const int* in_sizes, int n_in,
                              void* d_out, int out_size) {
    const float* u       = (const float*)d_in[0];
    const float* W_in    = (const float*)d_in[1];
    const float* conv_w  = (const float*)d_in[2];
    const float* conv_b  = (const float*)d_in[3];
    const float* W_rxbc  = (const float*)d_in[4];
    const float* W_rdt   = (const float*)d_in[5];
    const float* dt_bias = (const float*)d_in[6];
    const float* A_log   = (const float*)d_in[7];
    const float* D_param = (const float*)d_in[8];
    const float* norm_w  = (const float*)d_in[9];
    const float* W_out   = (const float*)d_in[10];
    float* out = (float*)d_out;

    static int attr_set = 0;
    const int SCAN_SMEM = SM_TOTALF * 4;
    const int IP_SMEM   = IP_TOTALF * 4;
    if (!attr_set) {
        cudaFuncSetAttribute(scan_kernel, cudaFuncAttributeMaxDynamicSharedMemorySize, SCAN_SMEM);
        cudaFuncSetAttribute(inproj_kernel, cudaFuncAttributeMaxDynamicSharedMemorySize, IP_SMEM);
        attr_set = 1;
    }

    wfrag_kernel<<<8192, 256>>>(W_rxbc, W_rdt, W_out);

    dim3 gIn((DINPROJ + 63) / 64, (BATCH * SEQLEN) / 128);
    inproj_kernel<<<gIn, 256, IP_SMEM>>>(u, W_in);

    int convN = BATCH * SEQLEN * CONVDIM;
    conv_kernel<<<(convN + 255) / 256, 256>>>(conv_w, conv_b);

    scan_kernel<<<NCTA, NTHR, SCAN_SMEM>>>(dt_bias, A_log, D_param, norm_w, out);
}

// round 13
// speedup vs baseline: 1.3228x; 1.3228x over previous
#include <cuda_runtime.h>
#include <cuda_bf16.h>
#include <math.h>

// ---------------- problem constants ----------------
#define BATCH     16
#define SEQLEN    512
#define DMODEL    1024
#define DSTATE    128
#define DCONV     4
#define HEADDIM   64
#define DSSM      2048
#define NHEADS    32
#define CONVDIM   2304            // DSSM + 2*DSTATE
#define DINPROJ   4384            // 2*DSSM + 2*DSTATE + NHEADS
#define ACTDIM    2336            // CONVDIM + NHEADS
#define NCTA      128
#define NTHR      512
#define EPSV      1e-5f

// scan SMEM layout (floats)
#define SM_STATE  0                        // 256*132 = 33792 (state[p][n], pad 132)
#define SM_Y      33792                    // 16*512 = 8192 (warp partials / scratch)
#define SM_BC     (33792 + 8192)           // 1024
#define SM_RED    (33792 + 8192 + 1024)    // 32
#define SM_TOTALF (33792 + 8192 + 1024 + 32)

// ---------------- device scratch ----------------
__device__ float g_zxbcdt[BATCH * SEQLEN * DINPROJ];
__device__ float g_xbcconv[BATCH * SEQLEN * CONVDIM];
__device__ float g_act[BATCH * ACTDIM];
__device__ float g_mspart[BATCH * 32];          // per (batch, head) sum of g^2
__device__ unsigned g_arrive[NCTA * 32];        // padded per-CTA epoch flags (monotonic)
__device__ unsigned g_release;                  // epoch base carrier across replays
// W fragments: [cta][s(128)][hilo(2)][lane(32)][nt(4)][b0,b1] as u32 -> 32 MB
__device__ unsigned g_wfrag[128 * 128 * 2 * 256];
// Y fragments: [hilo][s(128)][lane(32)][reg(4)] as u32 (bf16x2) -> 128 KB
__device__ unsigned g_yfrag[2 * 128 * 32 * 4];

// ---------------- helpers ----------------
__device__ __forceinline__ float silu_f(float v) { return v / (1.0f + expf(-v)); }
__device__ __forceinline__ float softplus_f(float v) { return (v > 20.0f) ? v : log1pf(expf(v)); }

__device__ __forceinline__ void upk2(unsigned long long v, float& lo, float& hi) {
    unsigned a, b;
    asm("mov.b64 {%0, %1}, %2;" : "=r"(a), "=r"(b) : "l"(v));
    lo = __uint_as_float(a); hi = __uint_as_float(b);
}
__device__ __forceinline__ unsigned long long pk2(float lo, float hi) {
    unsigned long long r;
    asm("mov.b64 %0, {%1, %2};" : "=l"(r) : "r"(__float_as_uint(lo)), "r"(__float_as_uint(hi)));
    return r;
}
__device__ __forceinline__ unsigned long long fma2(unsigned long long a, unsigned long long b,
                                                   unsigned long long c) {
    unsigned long long d;
    asm("fma.rn.f32x2 %0, %1, %2, %3;" : "=l"(d) : "l"(a), "l"(b), "l"(c));
    return d;
}
__device__ __forceinline__ unsigned long long mul2(unsigned long long a, unsigned long long b) {
    unsigned long long d;
    asm("mul.rn.f32x2 %0, %1, %2;" : "=l"(d) : "l"(a), "l"(b));
    return d;
}
__device__ __forceinline__ unsigned tf32_of(float x) {
    unsigned r;
    asm("cvt.rna.tf32.f32 %0, %1;" : "=r"(r) : "f"(x));
    return r;
}

// ---- strong flag ops (barrier protocol; unchanged, proven) ----
__device__ __forceinline__ void st_release_u(unsigned* p, unsigned v) {
    asm volatile("st.release.gpu.global.u32 [%0], %1;" :: "l"(p), "r"(v) : "memory");
}
__device__ __forceinline__ unsigned ld_acquire_u(const unsigned* p) {
    unsigned v;
    asm volatile("ld.acquire.gpu.global.u32 %0, [%1];" : "=r"(v) : "l"(p) : "memory");
    return v;
}
// ---- mutable-data stores: volatile relaxed (drain path proven by R7-R11) ----
__device__ __forceinline__ void st_rlx_f(float* p, float v) {
    asm volatile("st.relaxed.gpu.global.f32 [%0], %1;" :: "l"(p), "f"(v) : "memory");
}
__device__ __forceinline__ void st_rlx_u(unsigned* p, unsigned v) {
    asm volatile("st.relaxed.gpu.global.u32 [%0], %1;" :: "l"(p), "r"(v) : "memory");
}
__device__ __forceinline__ void st_rlx_b16(unsigned short* p, unsigned short v) {
    asm volatile("st.relaxed.gpu.global.b16 [%0], %1;" :: "l"(p), "h"(v) : "memory");
}

union F4U { float4 f; unsigned long long u[2]; unsigned v[4]; };

// FLAT single-hop grid barrier: every CTA's first 128 threads poll all flags.
__device__ __forceinline__ void grid_barrier(int cta, unsigned epoch) {
    __syncthreads();
    if (threadIdx.x == 0) st_release_u(&g_arrive[cta * 32], epoch);
    if (threadIdx.x < 128) {
        while (ld_acquire_u(&g_arrive[threadIdx.x * 32]) < epoch) { }
    }
    __syncthreads();
}

// bf16 MMA: D[16x8] += A[16x16] * B[16x8]  (non-volatile: let ptxas schedule)
__device__ __forceinline__ void mma_bf16(float* d, const unsigned* a, unsigned b0, unsigned b1) {
    asm("mma.sync.aligned.m16n8k16.row.col.f32.bf16.bf16.f32 "
        "{%0,%1,%2,%3}, {%4,%5,%6,%7}, {%8,%9}, {%0,%1,%2,%3};"
        : "+f"(d[0]), "+f"(d[1]), "+f"(d[2]), "+f"(d[3])
        : "r"(a[0]), "r"(a[1]), "r"(a[2]), "r"(a[3]), "r"(b0), "r"(b1));
}

// ---------------- kernel 0: precompute W fragments (bf16 hi/lo split) ----------------
__global__ __launch_bounds__(256) void wfrag_kernel(const float* __restrict__ W_rxbc,
                                                    const float* __restrict__ W_rdt,
                                                    const float* __restrict__ W_out) {
    int idx = blockIdx.x * 256 + threadIdx.x;      // < 128*128*32*4
    int nt   = idx & 3;
    int lane = (idx >> 2) & 31;
    int s    = (idx >> 7) & 127;
    int cta  = idx >> 14;
    int hasdt = (cta < NHEADS) ? 1 : 0;
    int ntask = 18 + hasdt + 8;
    int n_local = nt * 8 + (lane >> 2);
    int k0 = s * 16 + (lane & 3) * 2;

    float w00 = 0.f, w01 = 0.f, w10 = 0.f, w11 = 0.f;
    if (n_local < ntask) {
        const float* p;
        if (n_local < 18) p = W_rxbc + (size_t)(cta * 18 + n_local) * DSSM;
        else if (hasdt && n_local == 18) p = W_rdt + (size_t)cta * DSSM;
        else p = W_out + (size_t)(cta * 8 + n_local - 18 - hasdt) * DSSM;
        w00 = p[k0]; w01 = p[k0 + 1]; w10 = p[k0 + 8]; w11 = p[k0 + 9];
    }

    unsigned short h00, l00, h01, l01, h10, l10, h11, l11;
    {
        __nv_bfloat16 h;
        h = __float2bfloat16(w00); h00 = __bfloat16_as_ushort(h);
        l00 = __bfloat16_as_ushort(__float2bfloat16(w00 - __bfloat162float(h)));
        h = __float2bfloat16(w01); h01 = __bfloat16_as_ushort(h);
        l01 = __bfloat16_as_ushort(__float2bfloat16(w01 - __bfloat162float(h)));
        h = __float2bfloat16(w10); h10 = __bfloat16_as_ushort(h);
        l10 = __bfloat16_as_ushort(__float2bfloat16(w10 - __bfloat162float(h)));
        h = __float2bfloat16(w11); h11 = __bfloat16_as_ushort(h);
        l11 = __bfloat16_as_ushort(__float2bfloat16(w11 - __bfloat162float(h)));
    }

    size_t basehi = ((size_t)(cta * 128 + s) * 2) * 256 + lane * 8 + nt * 2;
    g_wfrag[basehi]       = (unsigned)h00 | ((unsigned)h01 << 16);
    g_wfrag[basehi + 1]   = (unsigned)h10 | ((unsigned)h11 << 16);
    g_wfrag[basehi + 256] = (unsigned)l00 | ((unsigned)l01 << 16);
    g_wfrag[basehi + 257] = (unsigned)l10 | ((unsigned)l11 << 16);
}

// ---------------- kernel 1: in_proj GEMM, tf32 mma (unchanged) --------
#define ASTR 36
#define IP_AH 0
#define IP_AL (2 * 128 * ASTR)
#define IP_BH (4 * 128 * ASTR)
#define IP_BL (4 * 128 * ASTR + 2 * 64 * ASTR)
#define IP_TOTALF (4 * 128 * ASTR + 4 * 64 * ASTR)

__device__ __forceinline__ void mma_tf32(float* d, const unsigned* a, const unsigned* b) {
    asm volatile(
        "mma.sync.aligned.m16n8k8.row.col.f32.tf32.tf32.f32 "
        "{%0,%1,%2,%3}, {%4,%5,%6,%7}, {%8,%9}, {%0,%1,%2,%3};"
        : "+f"(d[0]), "+f"(d[1]), "+f"(d[2]), "+f"(d[3])
        : "r"(a[0]), "r"(a[1]), "r"(a[2]), "r"(a[3]), "r"(b[0]), "r"(b[1]));
}

__global__ __launch_bounds__(256) void inproj_kernel(const float* __restrict__ U,
                                                     const float* __restrict__ Win) {
    extern __shared__ float smf[];
    const int N = DINPROJ;
    const int K = DMODEL;

    const int tid  = threadIdx.x;
    const int lane = tid & 31;
    const int warp = tid >> 5;
    const int mbase = blockIdx.y * 128;
    const int nbase = blockIdx.x * 64;
    const int mrow0 = (warp & 3) * 32;
    const int ncol0 = (warp >> 2) * 32;

    const int arow = tid >> 1;
    const int acb  = (tid & 1) * 16;
    const int brow = tid >> 2;
    const int bcb  = (tid & 3) * 8;

    float C[2][4][4];
#pragma unroll
    for (int mt = 0; mt < 2; mt++)
#pragma unroll
        for (int nt = 0; nt < 4; nt++)
#pragma unroll
            for (int e = 0; e < 4; e++) C[mt][nt][e] = 0.0f;

    float4 aReg[4];
    float4 bReg[2];

    auto ldg_chunk = [&](int k0) {
#pragma unroll
        for (int q = 0; q < 4; q++)
            aReg[q] = *(const float4*)(U + (mbase + arow) * K + k0 + acb + q * 4);
        if (nbase + brow < N) {
#pragma unroll
            for (int q = 0; q < 2; q++)
                bReg[q] = *(const float4*)(Win + (nbase + brow) * K + k0 + bcb + q * 4);
        } else {
            bReg[0] = make_float4(0.f, 0.f, 0.f, 0.f);
            bReg[1] = make_float4(0.f, 0.f, 0.f, 0.f);
        }
    };

    auto sts_chunk = [&](int buf) {
        float* Ah = smf + IP_AH + buf * 128 * ASTR;
        float* Al = smf + IP_AL + buf * 128 * ASTR;
        float* Bh = smf + IP_BH + buf * 64 * ASTR;
        float* Bl = smf + IP_BL + buf * 64 * ASTR;
#pragma unroll
        for (int q = 0; q < 4; q++) {
            const float* v = (const float*)&aReg[q];
#pragma unroll
            for (int e = 0; e < 4; e++) {
                float x = v[e];
                unsigned hb = tf32_of(x);
                float hf = __uint_as_float(hb);
                unsigned lb = tf32_of(x - hf);
                Ah[arow * ASTR + acb + q * 4 + e] = hf;
                Al[arow * ASTR + acb + q * 4 + e] = __uint_as_float(lb);
            }
        }
#pragma unroll
        for (int q = 0; q < 2; q++) {
            const float* v = (const float*)&bReg[q];
#pragma unroll
            for (int e = 0; e < 4; e++) {
                float x = v[e];
                unsigned hb = tf32_of(x);
                float hf = __uint_as_float(hb);
                unsigned lb = tf32_of(x - hf);
                Bh[brow * ASTR + bcb + q * 4 + e] = hf;
                Bl[brow * ASTR + bcb + q * 4 + e] = __uint_as_float(lb);
            }
        }
    };

    ldg_chunk(0);
    sts_chunk(0);
    __syncthreads();

    const int NCHUNK = K / 32;
    for (int c = 0; c < NCHUNK; c++) {
        int buf = c & 1;
        if (c + 1 < NCHUNK) ldg_chunk((c + 1) * 32);

        const unsigned* Ah = (const unsigned*)(smf + IP_AH + buf * 128 * ASTR);
        const unsigned* Al = (const unsigned*)(smf + IP_AL + buf * 128 * ASTR);
        const unsigned* Bh = (const unsigned*)(smf + IP_BH + buf * 64 * ASTR);
        const unsigned* Bl = (const unsigned*)(smf + IP_BL + buf * 64 * ASTR);

#pragma unroll
        for (int ks = 0; ks < 4; ks++) {
            int kc = ks * 8;
            unsigned ah[2][4], al[2][4], bh[4][2], bl[4][2];
#pragma unroll
            for (int mt = 0; mt < 2; mt++) {
                int r0 = mrow0 + mt * 16 + (lane >> 2);
                int cc = kc + (lane & 3);
                ah[mt][0] = Ah[r0 * ASTR + cc];
                ah[mt][1] = Ah[(r0 + 8) * ASTR + cc];
                ah[mt][2] = Ah[r0 * ASTR + cc + 4];
                ah[mt][3] = Ah[(r0 + 8) * ASTR + cc + 4];
                al[mt][0] = Al[r0 * ASTR + cc];
                al[mt][1] = Al[(r0 + 8) * ASTR + cc];
                al[mt][2] = Al[r0 * ASTR + cc + 4];
                al[mt][3] = Al[(r0 + 8) * ASTR + cc + 4];
            }
#pragma unroll
            for (int nt = 0; nt < 4; nt++) {
                int n0 = ncol0 + nt * 8 + (lane >> 2);
                int kk = kc + (lane & 3);
                bh[nt][0] = Bh[n0 * ASTR + kk];
                bh[nt][1] = Bh[n0 * ASTR + kk + 4];
                bl[nt][0] = Bl[n0 * ASTR + kk];
                bl[nt][1] = Bl[n0 * ASTR + kk + 4];
            }
#pragma unroll
            for (int mt = 0; mt < 2; mt++)
#pragma unroll
                for (int nt = 0; nt < 4; nt++) {
                    mma_tf32(C[mt][nt], ah[mt], bh[nt]);
                    mma_tf32(C[mt][nt], al[mt], bh[nt]);
                    mma_tf32(C[mt][nt], ah[mt], bl[nt]);
                }
        }

        __syncthreads();
        if (c + 1 < NCHUNK) {
            sts_chunk(buf ^ 1);
            __syncthreads();
        }
    }

#pragma unroll
    for (int mt = 0; mt < 2; mt++) {
        int row = mbase + mrow0 + mt * 16 + (lane >> 2);
#pragma unroll
        for (int nt = 0; nt < 4; nt++) {
            int col = nbase + ncol0 + nt * 8 + (lane & 3) * 2;
            if (col < N) {
                g_zxbcdt[row * N + col]           = C[mt][nt][0];
                g_zxbcdt[row * N + col + 1]       = C[mt][nt][1];
                g_zxbcdt[(row + 8) * N + col]     = C[mt][nt][2];
                g_zxbcdt[(row + 8) * N + col + 1] = C[mt][nt][3];
            }
        }
    }
}

// ---------------- kernel 2: causal depthwise conv ----------------
__global__ __launch_bounds__(256) void conv_kernel(const float* __restrict__ conv_w,
                                                   const float* __restrict__ conv_b) {
    int idx = blockIdx.x * blockDim.x + threadIdx.x;
    if (idx >= BATCH * SEQLEN * CONVDIM) return;
    int c  = idx % CONVDIM;
    int bt = idx / CONVDIM;
    int t  = bt % SEQLEN;
    int b  = bt / SEQLEN;
    float accv = conv_b[c];
#pragma unroll
    for (int k = 0; k < DCONV; k++) {
        int tt = t + k - (DCONV - 1);
        if (tt >= 0)
            accv = fmaf(g_zxbcdt[(b * SEQLEN + tt) * DINPROJ + DSSM + c],
                        conv_w[c * DCONV + k], accv);
    }
    g_xbcconv[idx] = accv;
}

// ---------------- kernel 3: persistent scan, 512 threads, __ldcg data loads ----------------
__global__ __launch_bounds__(NTHR, 1) void scan_kernel(
    const float* __restrict__ dt_bias, const float* __restrict__ A_log,
    const float* __restrict__ D_param, const float* __restrict__ norm_w,
    float* __restrict__ out) {

    extern __shared__ float sm[];
    float* s_state = sm + SM_STATE;       // state[p][n], p = b_loc*64+dd, stride 132
    float* s_y     = sm + SM_Y;           // 16 warps x 512 partials / phase-B scratch
    float* s_bc    = sm + SM_BC;
    float* s_red   = sm + SM_RED;
    __shared__ unsigned s_base;

    const int tid  = threadIdx.x;
    const int cta  = blockIdx.x;
    const int lane = tid & 31;
    const int warp = tid >> 5;

    if (tid == 0) s_base = ld_acquire_u(&g_release);
    {
        int i = cta * NTHR + tid;
        if (i < 2 * 128 * 32 * 4) st_rlx_u(&g_yfrag[i], 0u);
    }
    for (int i = tid; i < 256 * 132; i += NTHR) s_state[i] = 0.0f;
    __syncthreads();
    unsigned epoch = s_base + 1;

    const int hasdt = (cta < NHEADS) ? 1 : 0;
    const int ntask = 18 + hasdt + 8;

    // ---- phase B mapping: p = tid & 255, half = tid >> 8 ----
    const int p     = tid & 255;
    const int half  = tid >> 8;
    const int h  = cta & 31;
    const int bg = cta >> 5;
    const int b_loc = p >> 6;
    const int dd    = p & 63;
    const int bglb  = bg * 4 + b_loc;
    const float Ah  = -expf(A_log[h]);
    const float dtb = dt_bias[h];
    const float Dh  = D_param[h];
    const float nw  = norm_w[h * HEADDIM + dd];
    const int n0    = half * 64;

    // Y-frag slot (based on p; only half==0 writes)
    int yk = h * HEADDIM + dd;
    int ys = yk >> 4;
    int yc = yk & 15;
    int yreg = ((yc >= 8) ? 2 : 0) + ((bglb >= 8) ? 1 : 0);
    int yln  = ((bglb & 7) << 2) | ((yc >> 1) & 3);
    int yhalf = yc & 1;
    unsigned short* yb16 = (unsigned short*)g_yfrag;
    int ywi = ((ys * 32 + yln) * 4 + yreg) * 2 + yhalf;

    // rsqrt loader mapping (tid < 128): batch rb = tid>>3, quarter rq = tid&7
    const int rb = tid >> 3;
    const int rq = tid & 7;

    grid_barrier(cta, epoch++);

    for (int t = 0; t <= SEQLEN; t++) {
        // =================== phase A: D[16,32] = Y @ W^T, pipelined ===========
        if (tid < 128) {
            float4 v = __ldcg((const float4*)(g_mspart + rb * 32 + rq * 4));
            float s = (v.x + v.y) + (v.z + v.w);
            s += __shfl_xor_sync(0xffffffffu, s, 1);
            s += __shfl_xor_sync(0xffffffffu, s, 2);
            s += __shfl_xor_sync(0xffffffffu, s, 4);
            if (rq == 0) s_red[rb] = rsqrtf(s * (1.0f / (float)DSSM) + EPSV);
        }

        float acc[4][4];
#pragma unroll
        for (int nt = 0; nt < 4; nt++)
#pragma unroll
            for (int e = 0; e < 4; e++) acc[nt][e] = 0.0f;

        uint4 wb[2][4];
        F4U yhb[2], ylb[2];
        auto load_slice = [&](int buf, int sl) {
            int s = (warp << 3) + sl;
            const uint4* wph = (const uint4*)(g_wfrag + ((size_t)(cta * 128 + s) * 2) * 256 + lane * 8);
            const uint4* wpl = (const uint4*)(g_wfrag + ((size_t)(cta * 128 + s) * 2 + 1) * 256 + lane * 8);
            yhb[buf].f = __ldcg((const float4*)(g_yfrag + (s * 32 + lane) * 4));
            ylb[buf].f = __ldcg((const float4*)(g_yfrag + 16384 + (s * 32 + lane) * 4));
            wb[buf][0] = wph[0];
            wb[buf][1] = wph[1];
            wb[buf][2] = wpl[0];
            wb[buf][3] = wpl[1];
        };

        load_slice(0, 0);
#pragma unroll
        for (int sl = 0; sl < 8; sl++) {
            int cb = sl & 1;
            if (sl < 7) load_slice(cb ^ 1, sl + 1);    // prefetch next slice first

            mma_bf16(acc[0], yhb[cb].v, wb[cb][0].x, wb[cb][0].y);
            mma_bf16(acc[0], ylb[cb].v, wb[cb][0].x, wb[cb][0].y);
            mma_bf16(acc[0], yhb[cb].v, wb[cb][2].x, wb[cb][2].y);

            mma_bf16(acc[1], yhb[cb].v, wb[cb][0].z, wb[cb][0].w);
            mma_bf16(acc[1], ylb[cb].v, wb[cb][0].z, wb[cb][0].w);
            mma_bf16(acc[1], yhb[cb].v, wb[cb][2].z, wb[cb][2].w);

            mma_bf16(acc[2], yhb[cb].v, wb[cb][1].x, wb[cb][1].y);
            mma_bf16(acc[2], ylb[cb].v, wb[cb][1].x, wb[cb][1].y);
            mma_bf16(acc[2], yhb[cb].v, wb[cb][3].x, wb[cb][3].y);

            mma_bf16(acc[3], yhb[cb].v, wb[cb][1].z, wb[cb][1].w);
            mma_bf16(acc[3], ylb[cb].v, wb[cb][1].z, wb[cb][1].w);
            mma_bf16(acc[3], yhb[cb].v, wb[cb][3].z, wb[cb][3].w);
        }

        {
            int bq = lane >> 2;
            int c2 = (lane & 3) * 2;
            float* wp = s_y + warp * 512;
#pragma unroll
            for (int nt = 0; nt < 4; nt++) {
                *(float2*)(wp + bq * 32 + nt * 8 + c2)       = make_float2(acc[nt][0], acc[nt][1]);
                *(float2*)(wp + (bq + 8) * 32 + nt * 8 + c2) = make_float2(acc[nt][2], acc[nt][3]);
            }
        }
        __syncthreads();

        // reduce 16 warp planes; one group per thread
        {
            int g = tid;
            int b = g >> 5;
            int r = g & 31;
            if (r < ntask) {
                float sum = 0.0f;
#pragma unroll
                for (int w = 0; w < 16; w++) sum += s_y[w * 512 + g];
                float val = sum * s_red[b];
                if (r < 18) {
                    if (t < SEQLEN) {
                        int idxv = cta * 18 + r;
                        float base = g_xbcconv[(b * SEQLEN + t) * CONVDIM + idxv];
                        st_rlx_f(&g_act[b * ACTDIM + idxv], silu_f(base + val));
                    }
                } else if (hasdt && r == 18) {
                    if (t < SEQLEN) {
                        float base = g_zxbcdt[(b * SEQLEN + t) * DINPROJ + (DSSM + CONVDIM) + cta];
                        st_rlx_f(&g_act[b * ACTDIM + CONVDIM + cta], silu_f(base + val));
                    }
                } else {
                    int idxv = cta * 8 + (r - 18 - hasdt);
                    if (t >= 1) out[(b * SEQLEN + (t - 1)) * DMODEL + idxv] = val;
                }
            }
        }

        if (t == SEQLEN) break;

        grid_barrier(cta, epoch++);   // act(t) visible

        // =================== phase B (n-range split across halves) ===================
        float x   = __ldcg(&g_act[bglb * ACTDIM + h * HEADDIM + dd]);
        float dtr = __ldcg(&g_act[bglb * ACTDIM + CONVDIM + h]);
        float z   = g_zxbcdt[(bglb * SEQLEN + t) * DINPROJ + h * HEADDIM + dd];

        {
            int i = tid * 2;           // 512 threads x float2 = 1024 floats
            int bl = i >> 8, k = i & 255;
            float2 v = __ldcg((const float2*)&g_act[(bg * 4 + bl) * ACTDIM + DSSM + k]);
            *(float2*)(s_bc + i) = v;
        }
        __syncthreads();

        float g;
        {
            float dt_v = softplus_f(dtr + dtb);
            float dA  = expf(dt_v * Ah);
            float coef = dt_v * x;

            unsigned long long dA2 = pk2(dA, dA);
            unsigned long long cf2 = pk2(coef, coef);
            unsigned long long acc2 = 0ULL;

            const float* bvp = s_bc + b_loc * 256 + n0;
            const float* cvp = s_bc + b_loc * 256 + 128 + n0;
            float* sp = s_state + p * 132 + n0;
#pragma unroll 4
            for (int n = 0; n < 64; n += 4) {
                F4U sv, bv, cv;
                sv.f = *(float4*)(sp + n);
                bv.f = *(const float4*)(bvp + n);
                cv.f = *(const float4*)(cvp + n);
                sv.u[0] = fma2(sv.u[0], dA2, mul2(cf2, bv.u[0]));
                sv.u[1] = fma2(sv.u[1], dA2, mul2(cf2, bv.u[1]));
                acc2 = fma2(sv.u[0], cv.u[0], acc2);
                acc2 = fma2(sv.u[1], cv.u[1], acc2);
                *(float4*)(sp + n) = sv.f;
            }
            float alo, ahi;
            upk2(acc2, alo, ahi);
            s_y[tid] = alo + ahi;     // partial dot over this half's n-range
        }
        __syncthreads();

        if (half == 0) {
            float accv = s_y[tid] + s_y[tid + 256];
            float y = fmaf(Dh, x, accv);
            g = y * silu_f(z);

            // write Y fragment (bf16 hi/lo) for phase A(t+1)
            float yv = g * nw;
            __nv_bfloat16 hb = __float2bfloat16(yv);
            float hf = __bfloat162float(hb);
            __nv_bfloat16 lb = __float2bfloat16(yv - hf);
            st_rlx_b16(yb16 + ywi, __bfloat16_as_ushort(hb));
            st_rlx_b16(yb16 + 32768 + ywi, __bfloat16_as_ushort(lb));

            float gsq = g * g;
#pragma unroll
            for (int off = 16; off > 0; off >>= 1)
                gsq += __shfl_xor_sync(0xffffffffu, gsq, off);
            if (lane == 0) s_red[16 + warp] = gsq;   // warps 0..7
        }
        __syncthreads();

        if (tid < 4) {
            float part = s_red[16 + 2 * tid] + s_red[16 + 2 * tid + 1];
            st_rlx_f(&g_mspart[(bg * 4 + tid) * 32 + h], part);
        }

        grid_barrier(cta, epoch++);   // yfrags + partials visible
    }
}

// ---------------- launcher ----------------
extern "C" void kernel_launch(void* const* d_in, const int* in_sizes, int n_in,
                              void* d_out, int out_size) {
    const float* u       = (const float*)d_in[0];
    const float* W_in    = (const float*)d_in[1];
    const float* conv_w  = (const float*)d_in[2];
    const float* conv_b  = (const float*)d_in[3];
    const float* W_rxbc  = (const float*)d_in[4];
    const float* W_rdt   = (const float*)d_in[5];
    const float* dt_bias = (const float*)d_in[6];
    const float* A_log   = (const float*)d_in[7];
    const float* D_param = (const float*)d_in[8];
    const float* norm_w  = (const float*)d_in[9];
    const float* W_out   = (const float*)d_in[10];
    float* out = (float*)d_out;

    static int attr_set = 0;
    const int SCAN_SMEM = SM_TOTALF * 4;
    const int IP_SMEM   = IP_TOTALF * 4;
    if (!attr_set) {
        cudaFuncSetAttribute(scan_kernel, cudaFuncAttributeMaxDynamicSharedMemorySize, SCAN_SMEM);
        cudaFuncSetAttribute(inproj_kernel, cudaFuncAttributeMaxDynamicSharedMemorySize, IP_SMEM);
        attr_set = 1;
    }

    wfrag_kernel<<<8192, 256>>>(W_rxbc, W_rdt, W_out);

    dim3 gIn((DINPROJ + 63) / 64, (BATCH * SEQLEN) / 128);
    inproj_kernel<<<gIn, 256, IP_SMEM>>>(u, W_in);

    int convN = BATCH * SEQLEN * CONVDIM;
    conv_kernel<<<(convN + 255) / 256, 256>>>(conv_w, conv_b);

    scan_kernel<<<NCTA, NTHR, SCAN_SMEM>>>(dt_bias, A_log, D_param, norm_w, out);
}

// round 15
// speedup vs baseline: 1.3539x; 1.0235x over previous
#include <cuda_runtime.h>
#include <cuda_bf16.h>
#include <math.h>

// ---------------- problem constants ----------------
#define BATCH     16
#define SEQLEN    512
#define DMODEL    1024
#define DSTATE    128
#define DCONV     4
#define HEADDIM   64
#define DSSM      2048
#define NHEADS    32
#define CONVDIM   2304            // DSSM + 2*DSTATE
#define DINPROJ   4384            // 2*DSSM + 2*DSTATE + NHEADS
#define ACTDIM    2336            // CONVDIM + NHEADS
#define NCTA      128
#define NTHR      512
#define EPSV      1e-5f

// scan SMEM layout (floats)
#define SM_STATE  0                        // 256*132 = 33792 (state[p][n], pad 132)
#define SM_Y      33792                    // 16*512 = 8192 (warp partials / scratch)
#define SM_BC     (33792 + 8192)           // 1024
#define SM_RED    (33792 + 8192 + 1024)    // 32
#define SM_TOTALF (33792 + 8192 + 1024 + 32)

// ---------------- device scratch ----------------
__device__ float g_zxbcdt[BATCH * SEQLEN * DINPROJ];
__device__ float g_xbcconv[BATCH * SEQLEN * CONVDIM];
__device__ float g_act[BATCH * ACTDIM];
__device__ float g_mspart[BATCH * 32];          // per (batch, head) sum of g^2
__device__ unsigned g_arrive[NCTA * 32];        // padded per-CTA epoch flags
__device__ unsigned g_release;                  // epoch base carrier (as in R13)
// W fragments: [cta][s(128)][hilo(2)][lane(32)][nt(4)][b0,b1] as u32 -> 32 MB
__device__ unsigned g_wfrag[128 * 128 * 2 * 256];
// Y fragments: [hilo][s(128)][lane(32)][reg(4)] as u32 (bf16x2) -> 128 KB
__device__ unsigned g_yfrag[2 * 128 * 32 * 4];

// ---------------- helpers ----------------
__device__ __forceinline__ float silu_f(float v) { return v / (1.0f + expf(-v)); }
__device__ __forceinline__ float softplus_f(float v) { return (v > 20.0f) ? v : log1pf(expf(v)); }

__device__ __forceinline__ void upk2(unsigned long long v, float& lo, float& hi) {
    unsigned a, b;
    asm("mov.b64 {%0, %1}, %2;" : "=r"(a), "=r"(b) : "l"(v));
    lo = __uint_as_float(a); hi = __uint_as_float(b);
}
__device__ __forceinline__ unsigned long long pk2(float lo, float hi) {
    unsigned long long r;
    asm("mov.b64 %0, {%1, %2};" : "=l"(r) : "r"(__float_as_uint(lo)), "r"(__float_as_uint(hi)));
    return r;
}
__device__ __forceinline__ unsigned long long fma2(unsigned long long a, unsigned long long b,
                                                   unsigned long long c) {
    unsigned long long d;
    asm("fma.rn.f32x2 %0, %1, %2, %3;" : "=l"(d) : "l"(a), "l"(b), "l"(c));
    return d;
}
__device__ __forceinline__ unsigned long long mul2(unsigned long long a, unsigned long long b) {
    unsigned long long d;
    asm("mul.rn.f32x2 %0, %1, %2;" : "=l"(d) : "l"(a), "l"(b));
    return d;
}
__device__ __forceinline__ unsigned tf32_of(float x) {
    unsigned r;
    asm("cvt.rna.tf32.f32 %0, %1;" : "=r"(r) : "f"(x));
    return r;
}

// ---- strong flag ops (barrier protocol; proven) ----
__device__ __forceinline__ void st_release_u(unsigned* p, unsigned v) {
    asm volatile("st.release.gpu.global.u32 [%0], %1;" :: "l"(p), "r"(v) : "memory");
}
__device__ __forceinline__ unsigned ld_acquire_u(const unsigned* p) {
    unsigned v;
    asm volatile("ld.acquire.gpu.global.u32 %0, [%1];" : "=r"(v) : "l"(p) : "memory");
    return v;
}
// ---- mutable-data stores: volatile relaxed (proven drain path) ----
__device__ __forceinline__ void st_rlx_f(float* p, float v) {
    asm volatile("st.relaxed.gpu.global.f32 [%0], %1;" :: "l"(p), "f"(v) : "memory");
}
__device__ __forceinline__ void st_rlx_u(unsigned* p, unsigned v) {
    asm volatile("st.relaxed.gpu.global.u32 [%0], %1;" :: "l"(p), "r"(v) : "memory");
}
__device__ __forceinline__ void st_rlx_b16(unsigned short* p, unsigned short v) {
    asm volatile("st.relaxed.gpu.global.b16 [%0], %1;" :: "l"(p), "h"(v) : "memory");
}

union F4U { float4 f; unsigned long long u[2]; unsigned v[4]; };

// SPLIT-PHASE flat grid barrier (128 CTAs). Arrive publishes; wait polls.
// Between arrive and wait, only READ-ONLY data may be touched.
__device__ __forceinline__ void barrier_arrive(int cta, unsigned epoch) {
    __syncthreads();
    if (threadIdx.x == 0) st_release_u(&g_arrive[cta * 32], epoch);
}
__device__ __forceinline__ void barrier_wait(unsigned epoch) {
    if (threadIdx.x < 128) {
        while (ld_acquire_u(&g_arrive[threadIdx.x * 32]) < epoch) { }
    }
    __syncthreads();
}

// bf16 MMA: D[16x8] += A[16x16] * B[16x8]  (non-volatile: let ptxas schedule)
__device__ __forceinline__ void mma_bf16(float* d, const unsigned* a, unsigned b0, unsigned b1) {
    asm("mma.sync.aligned.m16n8k16.row.col.f32.bf16.bf16.f32 "
        "{%0,%1,%2,%3}, {%4,%5,%6,%7}, {%8,%9}, {%0,%1,%2,%3};"
        : "+f"(d[0]), "+f"(d[1]), "+f"(d[2]), "+f"(d[3])
        : "r"(a[0]), "r"(a[1]), "r"(a[2]), "r"(a[3]), "r"(b0), "r"(b1));
}

// ---------------- kernel 0: precompute W fragments (bf16 hi/lo split) ----------------
__global__ __launch_bounds__(256) void wfrag_kernel(const float* __restrict__ W_rxbc,
                                                    const float* __restrict__ W_rdt,
                                                    const float* __restrict__ W_out) {
    int idx = blockIdx.x * 256 + threadIdx.x;      // < 128*128*32*4
    int nt   = idx & 3;
    int lane = (idx >> 2) & 31;
    int s    = (idx >> 7) & 127;
    int cta  = idx >> 14;
    int hasdt = (cta < NHEADS) ? 1 : 0;
    int ntask = 18 + hasdt + 8;
    int n_local = nt * 8 + (lane >> 2);
    int k0 = s * 16 + (lane & 3) * 2;

    float w00 = 0.f, w01 = 0.f, w10 = 0.f, w11 = 0.f;
    if (n_local < ntask) {
        const float* p;
        if (n_local < 18) p = W_rxbc + (size_t)(cta * 18 + n_local) * DSSM;
        else if (hasdt && n_local == 18) p = W_rdt + (size_t)cta * DSSM;
        else p = W_out + (size_t)(cta * 8 + n_local - 18 - hasdt) * DSSM;
        w00 = p[k0]; w01 = p[k0 + 1]; w10 = p[k0 + 8]; w11 = p[k0 + 9];
    }

    unsigned short h00, l00, h01, l01, h10, l10, h11, l11;
    {
        __nv_bfloat16 h;
        h = __float2bfloat16(w00); h00 = __bfloat16_as_ushort(h);
        l00 = __bfloat16_as_ushort(__float2bfloat16(w00 - __bfloat162float(h)));
        h = __float2bfloat16(w01); h01 = __bfloat16_as_ushort(h);
        l01 = __bfloat16_as_ushort(__float2bfloat16(w01 - __bfloat162float(h)));
        h = __float2bfloat16(w10); h10 = __bfloat16_as_ushort(h);
        l10 = __bfloat16_as_ushort(__float2bfloat16(w10 - __bfloat162float(h)));
        h = __float2bfloat16(w11); h11 = __bfloat16_as_ushort(h);
        l11 = __bfloat16_as_ushort(__float2bfloat16(w11 - __bfloat162float(h)));
    }

    size_t basehi = ((size_t)(cta * 128 + s) * 2) * 256 + lane * 8 + nt * 2;
    g_wfrag[basehi]       = (unsigned)h00 | ((unsigned)h01 << 16);
    g_wfrag[basehi + 1]   = (unsigned)h10 | ((unsigned)h11 << 16);
    g_wfrag[basehi + 256] = (unsigned)l00 | ((unsigned)l01 << 16);
    g_wfrag[basehi + 257] = (unsigned)l10 | ((unsigned)l11 << 16);
}

// ---------------- kernel 1: in_proj GEMM, tf32 mma (unchanged) --------
#define ASTR 36
#define IP_AH 0
#define IP_AL (2 * 128 * ASTR)
#define IP_BH (4 * 128 * ASTR)
#define IP_BL (4 * 128 * ASTR + 2 * 64 * ASTR)
#define IP_TOTALF (4 * 128 * ASTR + 4 * 64 * ASTR)

__device__ __forceinline__ void mma_tf32(float* d, const unsigned* a, const unsigned* b) {
    asm volatile(
        "mma.sync.aligned.m16n8k8.row.col.f32.tf32.tf32.f32 "
        "{%0,%1,%2,%3}, {%4,%5,%6,%7}, {%8,%9}, {%0,%1,%2,%3};"
        : "+f"(d[0]), "+f"(d[1]), "+f"(d[2]), "+f"(d[3])
        : "r"(a[0]), "r"(a[1]), "r"(a[2]), "r"(a[3]), "r"(b[0]), "r"(b[1]));
}

__global__ __launch_bounds__(256) void inproj_kernel(const float* __restrict__ U,
                                                     const float* __restrict__ Win) {
    extern __shared__ float smf[];
    const int N = DINPROJ;
    const int K = DMODEL;

    const int tid  = threadIdx.x;
    const int lane = tid & 31;
    const int warp = tid >> 5;
    const int mbase = blockIdx.y * 128;
    const int nbase = blockIdx.x * 64;
    const int mrow0 = (warp & 3) * 32;
    const int ncol0 = (warp >> 2) * 32;

    const int arow = tid >> 1;
    const int acb  = (tid & 1) * 16;
    const int brow = tid >> 2;
    const int bcb  = (tid & 3) * 8;

    float C[2][4][4];
#pragma unroll
    for (int mt = 0; mt < 2; mt++)
#pragma unroll
        for (int nt = 0; nt < 4; nt++)
#pragma unroll
            for (int e = 0; e < 4; e++) C[mt][nt][e] = 0.0f;

    float4 aReg[4];
    float4 bReg[2];

    auto ldg_chunk = [&](int k0) {
#pragma unroll
        for (int q = 0; q < 4; q++)
            aReg[q] = *(const float4*)(U + (mbase + arow) * K + k0 + acb + q * 4);
        if (nbase + brow < N) {
#pragma unroll
            for (int q = 0; q < 2; q++)
                bReg[q] = *(const float4*)(Win + (nbase + brow) * K + k0 + bcb + q * 4);
        } else {
            bReg[0] = make_float4(0.f, 0.f, 0.f, 0.f);
            bReg[1] = make_float4(0.f, 0.f, 0.f, 0.f);
        }
    };

    auto sts_chunk = [&](int buf) {
        float* Ah = smf + IP_AH + buf * 128 * ASTR;
        float* Al = smf + IP_AL + buf * 128 * ASTR;
        float* Bh = smf + IP_BH + buf * 64 * ASTR;
        float* Bl = smf + IP_BL + buf * 64 * ASTR;
#pragma unroll
        for (int q = 0; q < 4; q++) {
            const float* v = (const float*)&aReg[q];
#pragma unroll
            for (int e = 0; e < 4; e++) {
                float x = v[e];
                unsigned hb = tf32_of(x);
                float hf = __uint_as_float(hb);
                unsigned lb = tf32_of(x - hf);
                Ah[arow * ASTR + acb + q * 4 + e] = hf;
                Al[arow * ASTR + acb + q * 4 + e] = __uint_as_float(lb);
            }
        }
#pragma unroll
        for (int q = 0; q < 2; q++) {
            const float* v = (const float*)&bReg[q];
#pragma unroll
            for (int e = 0; e < 4; e++) {
                float x = v[e];
                unsigned hb = tf32_of(x);
                float hf = __uint_as_float(hb);
                unsigned lb = tf32_of(x - hf);
                Bh[brow * ASTR + bcb + q * 4 + e] = hf;
                Bl[brow * ASTR + bcb + q * 4 + e] = __uint_as_float(lb);
            }
        }
    };

    ldg_chunk(0);
    sts_chunk(0);
    __syncthreads();

    const int NCHUNK = K / 32;
    for (int c = 0; c < NCHUNK; c++) {
        int buf = c & 1;
        if (c + 1 < NCHUNK) ldg_chunk((c + 1) * 32);

        const unsigned* Ah = (const unsigned*)(smf + IP_AH + buf * 128 * ASTR);
        const unsigned* Al = (const unsigned*)(smf + IP_AL + buf * 128 * ASTR);
        const unsigned* Bh = (const unsigned*)(smf + IP_BH + buf * 64 * ASTR);
        const unsigned* Bl = (const unsigned*)(smf + IP_BL + buf * 64 * ASTR);

#pragma unroll
        for (int ks = 0; ks < 4; ks++) {
            int kc = ks * 8;
            unsigned ah[2][4], al[2][4], bh[4][2], bl[4][2];
#pragma unroll
            for (int mt = 0; mt < 2; mt++) {
                int r0 = mrow0 + mt * 16 + (lane >> 2);
                int cc = kc + (lane & 3);
                ah[mt][0] = Ah[r0 * ASTR + cc];
                ah[mt][1] = Ah[(r0 + 8) * ASTR + cc];
                ah[mt][2] = Ah[r0 * ASTR + cc + 4];
                ah[mt][3] = Ah[(r0 + 8) * ASTR + cc + 4];
                al[mt][0] = Al[r0 * ASTR + cc];
                al[mt][1] = Al[(r0 + 8) * ASTR + cc];
                al[mt][2] = Al[r0 * ASTR + cc + 4];
                al[mt][3] = Al[(r0 + 8) * ASTR + cc + 4];
            }
#pragma unroll
            for (int nt = 0; nt < 4; nt++) {
                int n0 = ncol0 + nt * 8 + (lane >> 2);
                int kk = kc + (lane & 3);
                bh[nt][0] = Bh[n0 * ASTR + kk];
                bh[nt][1] = Bh[n0 * ASTR + kk + 4];
                bl[nt][0] = Bl[n0 * ASTR + kk];
                bl[nt][1] = Bl[n0 * ASTR + kk + 4];
            }
#pragma unroll
            for (int mt = 0; mt < 2; mt++)
#pragma unroll
                for (int nt = 0; nt < 4; nt++) {
                    mma_tf32(C[mt][nt], ah[mt], bh[nt]);
                    mma_tf32(C[mt][nt], al[mt], bh[nt]);
                    mma_tf32(C[mt][nt], ah[mt], bl[nt]);
                }
        }

        __syncthreads();
        if (c + 1 < NCHUNK) {
            sts_chunk(buf ^ 1);
            __syncthreads();
        }
    }

#pragma unroll
    for (int mt = 0; mt < 2; mt++) {
        int row = mbase + mrow0 + mt * 16 + (lane >> 2);
#pragma unroll
        for (int nt = 0; nt < 4; nt++) {
            int col = nbase + ncol0 + nt * 8 + (lane & 3) * 2;
            if (col < N) {
                g_zxbcdt[row * N + col]           = C[mt][nt][0];
                g_zxbcdt[row * N + col + 1]       = C[mt][nt][1];
                g_zxbcdt[(row + 8) * N + col]     = C[mt][nt][2];
                g_zxbcdt[(row + 8) * N + col + 1] = C[mt][nt][3];
            }
        }
    }
}

// ---------------- kernel 2: causal depthwise conv ----------------
__global__ __launch_bounds__(256) void conv_kernel(const float* __restrict__ conv_w,
                                                   const float* __restrict__ conv_b) {
    int idx = blockIdx.x * blockDim.x + threadIdx.x;
    if (idx >= BATCH * SEQLEN * CONVDIM) return;
    int c  = idx % CONVDIM;
    int bt = idx / CONVDIM;
    int t  = bt % SEQLEN;
    int b  = bt / SEQLEN;
    float accv = conv_b[c];
#pragma unroll
    for (int k = 0; k < DCONV; k++) {
        int tt = t + k - (DCONV - 1);
        if (tt >= 0)
            accv = fmaf(g_zxbcdt[(b * SEQLEN + tt) * DINPROJ + DSSM + c],
                        conv_w[c * DCONV + k], accv);
    }
    g_xbcconv[idx] = accv;
}

// ---------------- kernel 3: persistent scan, split-phase barriers ----------------
__global__ __launch_bounds__(NTHR, 1) void scan_kernel(
    const float* __restrict__ dt_bias, const float* __restrict__ A_log,
    const float* __restrict__ D_param, const float* __restrict__ norm_w,
    float* __restrict__ out) {

    extern __shared__ float sm[];
    float* s_state = sm + SM_STATE;       // state[p][n], p = b_loc*64+dd, stride 132
    float* s_y     = sm + SM_Y;           // 16 warps x 512 partials / phase-B scratch
    float* s_bc    = sm + SM_BC;
    float* s_red   = sm + SM_RED;
    __shared__ unsigned s_base;

    const int tid  = threadIdx.x;
    const int cta  = blockIdx.x;
    const int lane = tid & 31;
    const int warp = tid >> 5;

    if (tid == 0) s_base = ld_acquire_u(&g_release);
    {
        int i = cta * NTHR + tid;
        if (i < 2 * 128 * 32 * 4) st_rlx_u(&g_yfrag[i], 0u);
    }
    for (int i = tid; i < 256 * 132; i += NTHR) s_state[i] = 0.0f;
    __syncthreads();
    unsigned epoch = s_base + 1;

    const int hasdt = (cta < NHEADS) ? 1 : 0;
    const int ntask = 18 + hasdt + 8;

    // ---- phase B mapping: p = tid & 255, half = tid >> 8 ----
    const int p     = tid & 255;
    const int half  = tid >> 8;
    const int h  = cta & 31;
    const int bg = cta >> 5;
    const int b_loc = p >> 6;
    const int dd    = p & 63;
    const int bglb  = bg * 4 + b_loc;
    const float Ah  = -expf(A_log[h]);
    const float dtb = dt_bias[h];
    const float Dh  = D_param[h];
    const float nw  = norm_w[h * HEADDIM + dd];
    const int n0    = half * 64;

    // Y-frag slot (based on p; only half==0 writes)
    int yk = h * HEADDIM + dd;
    int ys = yk >> 4;
    int yc = yk & 15;
    int yreg = ((yc >= 8) ? 2 : 0) + ((bglb >= 8) ? 1 : 0);
    int yln  = ((bglb & 7) << 2) | ((yc >> 1) & 3);
    int yhalf = yc & 1;
    unsigned short* yb16 = (unsigned short*)g_yfrag;
    int ywi = ((ys * 32 + yln) * 4 + yreg) * 2 + yhalf;

    // rsqrt loader mapping (tid < 128): batch rb = tid>>3, quarter rq = tid&7
    const int rb = tid >> 3;
    const int rq = tid & 7;

    barrier_arrive(cta, epoch);
    unsigned ewait = epoch;          // init barrier; waited at top of t=0

    for (int t = 0; t <= SEQLEN; t++) {
        // =================== phase A: D[16,32] = Y @ W^T, pipelined ===========
        uint4 wb[2][4];
        F4U yhb[2], ylb[2];
        auto load_w = [&](int buf, int sl) {
            int s = (warp << 3) + sl;
            const uint4* wph = (const uint4*)(g_wfrag + ((size_t)(cta * 128 + s) * 2) * 256 + lane * 8);
            const uint4* wpl = (const uint4*)(g_wfrag + ((size_t)(cta * 128 + s) * 2 + 1) * 256 + lane * 8);
            wb[buf][0] = wph[0];
            wb[buf][1] = wph[1];
            wb[buf][2] = wpl[0];
            wb[buf][3] = wpl[1];
        };
        auto load_y = [&](int buf, int sl) {
            int s = (warp << 3) + sl;
            yhb[buf].f = __ldcg((const float4*)(g_yfrag + (s * 32 + lane) * 4));
            ylb[buf].f = __ldcg((const float4*)(g_yfrag + 16384 + (s * 32 + lane) * 4));
        };

        // pre-wait: W slice 0 prefetch (read-only), then wait for yfrag(t-1)
        load_w(0, 0);
        barrier_wait(ewait);
        load_y(0, 0);

        float acc[4][4];
#pragma unroll
        for (int nt = 0; nt < 4; nt++)
#pragma unroll
            for (int e = 0; e < 4; e++) acc[nt][e] = 0.0f;

#pragma unroll
        for (int sl = 0; sl < 8; sl++) {
            int cb = sl & 1;
            if (sl < 7) { load_w(cb ^ 1, sl + 1); load_y(cb ^ 1, sl + 1); }

            mma_bf16(acc[0], yhb[cb].v, wb[cb][0].x, wb[cb][0].y);
            mma_bf16(acc[0], ylb[cb].v, wb[cb][0].x, wb[cb][0].y);
            mma_bf16(acc[0], yhb[cb].v, wb[cb][2].x, wb[cb][2].y);

            mma_bf16(acc[1], yhb[cb].v, wb[cb][0].z, wb[cb][0].w);
            mma_bf16(acc[1], ylb[cb].v, wb[cb][0].z, wb[cb][0].w);
            mma_bf16(acc[1], yhb[cb].v, wb[cb][2].z, wb[cb][2].w);

            mma_bf16(acc[2], yhb[cb].v, wb[cb][1].x, wb[cb][1].y);
            mma_bf16(acc[2], ylb[cb].v, wb[cb][1].x, wb[cb][1].y);
            mma_bf16(acc[2], yhb[cb].v, wb[cb][3].x, wb[cb][3].y);

            mma_bf16(acc[3], yhb[cb].v, wb[cb][1].z, wb[cb][1].w);
            mma_bf16(acc[3], ylb[cb].v, wb[cb][1].z, wb[cb][1].w);
            mma_bf16(acc[3], yhb[cb].v, wb[cb][3].z, wb[cb][3].w);
        }

        {
            int bq = lane >> 2;
            int c2 = (lane & 3) * 2;
            float* wp = s_y + warp * 512;
#pragma unroll
            for (int nt = 0; nt < 4; nt++) {
                *(float2*)(wp + bq * 32 + nt * 8 + c2)       = make_float2(acc[nt][0], acc[nt][1]);
                *(float2*)(wp + (bq + 8) * 32 + nt * 8 + c2) = make_float2(acc[nt][2], acc[nt][3]);
            }
        }
        // rsqrt factors (reads g_mspart, gated by ewait) — hidden in store window
        if (tid < 128) {
            float4 v = __ldcg((const float4*)(g_mspart + rb * 32 + rq * 4));
            float s = (v.x + v.y) + (v.z + v.w);
            s += __shfl_xor_sync(0xffffffffu, s, 1);
            s += __shfl_xor_sync(0xffffffffu, s, 2);
            s += __shfl_xor_sync(0xffffffffu, s, 4);
            if (rq == 0) s_red[rb] = rsqrtf(s * (1.0f / (float)DSSM) + EPSV);
        }
        __syncthreads();

        // reduce 16 warp planes; one group per thread
        {
            int g = tid;
            int b = g >> 5;
            int r = g & 31;
            if (r < ntask) {
                float sum = 0.0f;
#pragma unroll
                for (int w = 0; w < 16; w++) sum += s_y[w * 512 + g];
                float val = sum * s_red[b];
                if (r < 18) {
                    if (t < SEQLEN) {
                        int idxv = cta * 18 + r;
                        float base = g_xbcconv[(b * SEQLEN + t) * CONVDIM + idxv];
                        st_rlx_f(&g_act[b * ACTDIM + idxv], silu_f(base + val));
                    }
                } else if (hasdt && r == 18) {
                    if (t < SEQLEN) {
                        float base = g_zxbcdt[(b * SEQLEN + t) * DINPROJ + (DSSM + CONVDIM) + cta];
                        st_rlx_f(&g_act[b * ACTDIM + CONVDIM + cta], silu_f(base + val));
                    }
                } else {
                    int idxv = cta * 8 + (r - 18 - hasdt);
                    if (t >= 1) out[(b * SEQLEN + (t - 1)) * DMODEL + idxv] = val;
                }
            }
        }

        if (t == SEQLEN) break;

        epoch++;
        barrier_arrive(cta, epoch);   // act(t) published
        // pre-wait read-only: z load
        float z = g_zxbcdt[(bglb * SEQLEN + t) * DINPROJ + h * HEADDIM + dd];
        barrier_wait(epoch);          // act(t) visible

        // =================== phase B (n-range split across halves) ===================
        float x   = __ldcg(&g_act[bglb * ACTDIM + h * HEADDIM + dd]);
        float dtr = __ldcg(&g_act[bglb * ACTDIM + CONVDIM + h]);

        {
            int i = tid * 2;           // 512 threads x float2 = 1024 floats
            int bl = i >> 8, k = i & 255;
            float2 v = __ldcg((const float2*)&g_act[(bg * 4 + bl) * ACTDIM + DSSM + k]);
            *(float2*)(s_bc + i) = v;
        }
        __syncthreads();

        float g;
        {
            float dt_v = softplus_f(dtr + dtb);
            float dA  = expf(dt_v * Ah);
            float coef = dt_v * x;

            unsigned long long dA2 = pk2(dA, dA);
            unsigned long long cf2 = pk2(coef, coef);
            unsigned long long acc2 = 0ULL;

            const float* bvp = s_bc + b_loc * 256 + n0;
            const float* cvp = s_bc + b_loc * 256 + 128 + n0;
            float* sp = s_state + p * 132 + n0;
#pragma unroll 4
            for (int n = 0; n < 64; n += 4) {
                F4U sv, bv, cv;
                sv.f = *(float4*)(sp + n);
                bv.f = *(const float4*)(bvp + n);
                cv.f = *(const float4*)(cvp + n);
                sv.u[0] = fma2(sv.u[0], dA2, mul2(cf2, bv.u[0]));
                sv.u[1] = fma2(sv.u[1], dA2, mul2(cf2, bv.u[1]));
                acc2 = fma2(sv.u[0], cv.u[0], acc2);
                acc2 = fma2(sv.u[1], cv.u[1], acc2);
                *(float4*)(sp + n) = sv.f;
            }
            float alo, ahi;
            upk2(acc2, alo, ahi);
            s_y[tid] = alo + ahi;     // partial dot over this half's n-range
        }
        __syncthreads();

        if (half == 0) {
            float accv = s_y[tid] + s_y[tid + 256];
            float y = fmaf(Dh, x, accv);
            g = y * silu_f(z);

            // write Y fragment (bf16 hi/lo) for phase A(t+1)
            float yv = g * nw;
            __nv_bfloat16 hb = __float2bfloat16(yv);
            float hf = __bfloat162float(hb);
            __nv_bfloat16 lb = __float2bfloat16(yv - hf);
            st_rlx_b16(yb16 + ywi, __bfloat16_as_ushort(hb));
            st_rlx_b16(yb16 + 32768 + ywi, __bfloat16_as_ushort(lb));

            float gsq = g * g;
#pragma unroll
            for (int off = 16; off > 0; off >>= 1)
                gsq += __shfl_xor_sync(0xffffffffu, gsq, off);
            if (lane == 0) s_red[16 + warp] = gsq;   // warps 0..7
        }
        __syncthreads();

        if (tid < 4) {
            float part = s_red[16 + 2 * tid] + s_red[16 + 2 * tid + 1];
            st_rlx_f(&g_mspart[(bg * 4 + tid) * 32 + h], part);
        }

        epoch++;
        barrier_arrive(cta, epoch);   // yfrag(t) + partials published
        ewait = epoch;                // waited at top of next iteration
    }
}

// ---------------- launcher ----------------
extern "C" void kernel_launch(void* const* d_in, const int* in_sizes, int n_in,
                              void* d_out, int out_size) {
    const float* u       = (const float*)d_in[0];
    const float* W_in    = (const float*)d_in[1];
    const float* conv_w  = (const float*)d_in[2];
    const float* conv_b  = (const float*)d_in[3];
    const float* W_rxbc  = (const float*)d_in[4];
    const float* W_rdt   = (const float*)d_in[5];
    const float* dt_bias = (const float*)d_in[6];
    const float* A_log   = (const float*)d_in[7];
    const float* D_param = (const float*)d_in[8];
    const float* norm_w  = (const float*)d_in[9];
    const float* W_out   = (const float*)d_in[10];
    float* out = (float*)d_out;

    static int attr_set = 0;
    const int SCAN_SMEM = SM_TOTALF * 4;
    const int IP_SMEM   = IP_TOTALF * 4;
    if (!attr_set) {
        cudaFuncSetAttribute(scan_kernel, cudaFuncAttributeMaxDynamicSharedMemorySize, SCAN_SMEM);
        cudaFuncSetAttribute(inproj_kernel, cudaFuncAttributeMaxDynamicSharedMemorySize, IP_SMEM);
        attr_set = 1;
    }

    wfrag_kernel<<<8192, 256>>>(W_rxbc, W_rdt, W_out);

    dim3 gIn((DINPROJ + 63) / 64, (BATCH * SEQLEN) / 128);
    inproj_kernel<<<gIn, 256, IP_SMEM>>>(u, W_in);

    int convN = BATCH * SEQLEN * CONVDIM;
    conv_kernel<<<(convN + 255) / 256, 256>>>(conv_w, conv_b);

    scan_kernel<<<NCTA, NTHR, SCAN_SMEM>>>(dt_bias, A_log, D_param, norm_w, out);
}

// round 16
// speedup vs baseline: 1.3647x; 1.0080x over previous
#include <cuda_runtime.h>
#include <cuda_bf16.h>
#include <math.h>

// ---------------- problem constants ----------------
#define BATCH     16
#define SEQLEN    512
#define DMODEL    1024
#define DSTATE    128
#define DCONV     4
#define HEADDIM   64
#define DSSM      2048
#define NHEADS    32
#define CONVDIM   2304            // DSSM + 2*DSTATE
#define DINPROJ   4384            // 2*DSSM + 2*DSTATE + NHEADS
#define ACTDIM    2336            // CONVDIM + NHEADS
#define NCTA      128
#define NTHR      512
#define EPSV      1e-5f

// scan SMEM layout (floats)
#define SM_STATE  0                        // 256*132 = 33792 (state[p][n], pad 132)
#define SM_Y      33792                    // 16*512 = 8192 (warp partials / scratch)
#define SM_BC     (33792 + 8192)           // 1024
#define SM_RED    (33792 + 8192 + 1024)    // 32
#define SM_TOTALF (33792 + 8192 + 1024 + 32)

// ---------------- device scratch ----------------
__device__ float g_zxbcdt[BATCH * SEQLEN * DINPROJ];
__device__ float g_xbcconv[BATCH * SEQLEN * CONVDIM];
__device__ float g_act[BATCH * ACTDIM];
__device__ float g_mspart[BATCH * 32];          // per (batch, head) sum of g^2
__device__ unsigned g_arrive[NCTA * 32];        // padded per-CTA epoch flags
__device__ unsigned g_release;                  // epoch base carrier
// W fragments: [cta][s(128)][hilo(2)][lane(32)][nt(4)][b0,b1] as u32 -> 32 MB
__device__ unsigned g_wfrag[128 * 128 * 2 * 256];
// Y fragments: [hilo][s(128)][lane(32)][reg(4)] as u32 (bf16x2) -> 128 KB
__device__ unsigned g_yfrag[2 * 128 * 32 * 4];

// ---------------- helpers ----------------
__device__ __forceinline__ float silu_f(float v) { return v / (1.0f + expf(-v)); }
__device__ __forceinline__ float softplus_f(float v) { return (v > 20.0f) ? v : log1pf(expf(v)); }

__device__ __forceinline__ void upk2(unsigned long long v, float& lo, float& hi) {
    unsigned a, b;
    asm("mov.b64 {%0, %1}, %2;" : "=r"(a), "=r"(b) : "l"(v));
    lo = __uint_as_float(a); hi = __uint_as_float(b);
}
__device__ __forceinline__ unsigned long long pk2(float lo, float hi) {
    unsigned long long r;
    asm("mov.b64 %0, {%1, %2};" : "=l"(r) : "r"(__float_as_uint(lo)), "r"(__float_as_uint(hi)));
    return r;
}
__device__ __forceinline__ unsigned long long fma2(unsigned long long a, unsigned long long b,
                                                   unsigned long long c) {
    unsigned long long d;
    asm("fma.rn.f32x2 %0, %1, %2, %3;" : "=l"(d) : "l"(a), "l"(b), "l"(c));
    return d;
}
__device__ __forceinline__ unsigned long long mul2(unsigned long long a, unsigned long long b) {
    unsigned long long d;
    asm("mul.rn.f32x2 %0, %1, %2;" : "=l"(d) : "l"(a), "l"(b));
    return d;
}
__device__ __forceinline__ unsigned tf32_of(float x) {
    unsigned r;
    asm("cvt.rna.tf32.f32 %0, %1;" : "=r"(r) : "f"(x));
    return r;
}

// ---- strong flag ops ----
__device__ __forceinline__ void st_release_u(unsigned* p, unsigned v) {
    asm volatile("st.release.gpu.global.u32 [%0], %1;" :: "l"(p), "r"(v) : "memory");
}
__device__ __forceinline__ unsigned ld_acquire_u(const unsigned* p) {
    unsigned v;
    asm volatile("ld.acquire.gpu.global.u32 %0, [%1];" : "=r"(v) : "l"(p) : "memory");
    return v;
}
// ---- mutable-data stores: volatile relaxed ----
__device__ __forceinline__ void st_rlx_f(float* p, float v) {
    asm volatile("st.relaxed.gpu.global.f32 [%0], %1;" :: "l"(p), "f"(v) : "memory");
}
__device__ __forceinline__ void st_rlx_u(unsigned* p, unsigned v) {
    asm volatile("st.relaxed.gpu.global.u32 [%0], %1;" :: "l"(p), "r"(v) : "memory");
}
__device__ __forceinline__ void st_rlx_b16(unsigned short* p, unsigned short v) {
    asm volatile("st.relaxed.gpu.global.b16 [%0], %1;" :: "l"(p), "h"(v) : "memory");
}

union F4U { float4 f; unsigned long long u[2]; unsigned v[4]; };

// SPLIT-PHASE flat grid barrier (128 CTAs).
__device__ __forceinline__ void barrier_arrive(int cta, unsigned epoch) {
    __syncthreads();
    if (threadIdx.x == 0) st_release_u(&g_arrive[cta * 32], epoch);
}
__device__ __forceinline__ void barrier_wait(unsigned epoch) {
    if (threadIdx.x < 128) {
        while (ld_acquire_u(&g_arrive[threadIdx.x * 32]) < epoch) { }
    }
    __syncthreads();
}

// bf16 MMA (non-volatile)
__device__ __forceinline__ void mma_bf16(float* d, const unsigned* a, unsigned b0, unsigned b1) {
    asm("mma.sync.aligned.m16n8k16.row.col.f32.bf16.bf16.f32 "
        "{%0,%1,%2,%3}, {%4,%5,%6,%7}, {%8,%9}, {%0,%1,%2,%3};"
        : "+f"(d[0]), "+f"(d[1]), "+f"(d[2]), "+f"(d[3])
        : "r"(a[0]), "r"(a[1]), "r"(a[2]), "r"(a[3]), "r"(b0), "r"(b1));
}

// ---------------- kernel 0: precompute W fragments (bf16 hi/lo split) ----------------
__global__ __launch_bounds__(256) void wfrag_kernel(const float* __restrict__ W_rxbc,
                                                    const float* __restrict__ W_rdt,
                                                    const float* __restrict__ W_out) {
    int idx = blockIdx.x * 256 + threadIdx.x;
    int nt   = idx & 3;
    int lane = (idx >> 2) & 31;
    int s    = (idx >> 7) & 127;
    int cta  = idx >> 14;
    int hasdt = (cta < NHEADS) ? 1 : 0;
    int ntask = 18 + hasdt + 8;
    int n_local = nt * 8 + (lane >> 2);
    int k0 = s * 16 + (lane & 3) * 2;

    float w00 = 0.f, w01 = 0.f, w10 = 0.f, w11 = 0.f;
    if (n_local < ntask) {
        const float* p;
        if (n_local < 18) p = W_rxbc + (size_t)(cta * 18 + n_local) * DSSM;
        else if (hasdt && n_local == 18) p = W_rdt + (size_t)cta * DSSM;
        else p = W_out + (size_t)(cta * 8 + n_local - 18 - hasdt) * DSSM;
        w00 = p[k0]; w01 = p[k0 + 1]; w10 = p[k0 + 8]; w11 = p[k0 + 9];
    }

    unsigned short h00, l00, h01, l01, h10, l10, h11, l11;
    {
        __nv_bfloat16 h;
        h = __float2bfloat16(w00); h00 = __bfloat16_as_ushort(h);
        l00 = __bfloat16_as_ushort(__float2bfloat16(w00 - __bfloat162float(h)));
        h = __float2bfloat16(w01); h01 = __bfloat16_as_ushort(h);
        l01 = __bfloat16_as_ushort(__float2bfloat16(w01 - __bfloat162float(h)));
        h = __float2bfloat16(w10); h10 = __bfloat16_as_ushort(h);
        l10 = __bfloat16_as_ushort(__float2bfloat16(w10 - __bfloat162float(h)));
        h = __float2bfloat16(w11); h11 = __bfloat16_as_ushort(h);
        l11 = __bfloat16_as_ushort(__float2bfloat16(w11 - __bfloat162float(h)));
    }

    size_t basehi = ((size_t)(cta * 128 + s) * 2) * 256 + lane * 8 + nt * 2;
    g_wfrag[basehi]       = (unsigned)h00 | ((unsigned)h01 << 16);
    g_wfrag[basehi + 1]   = (unsigned)h10 | ((unsigned)h11 << 16);
    g_wfrag[basehi + 256] = (unsigned)l00 | ((unsigned)l01 << 16);
    g_wfrag[basehi + 257] = (unsigned)l10 | ((unsigned)l11 << 16);
}

// ---------------- kernel 1: in_proj GEMM, tf32 mma (unchanged) --------
#define ASTR 36
#define IP_AH 0
#define IP_AL (2 * 128 * ASTR)
#define IP_BH (4 * 128 * ASTR)
#define IP_BL (4 * 128 * ASTR + 2 * 64 * ASTR)
#define IP_TOTALF (4 * 128 * ASTR + 4 * 64 * ASTR)

__device__ __forceinline__ void mma_tf32(float* d, const unsigned* a, const unsigned* b) {
    asm volatile(
        "mma.sync.aligned.m16n8k8.row.col.f32.tf32.tf32.f32 "
        "{%0,%1,%2,%3}, {%4,%5,%6,%7}, {%8,%9}, {%0,%1,%2,%3};"
        : "+f"(d[0]), "+f"(d[1]), "+f"(d[2]), "+f"(d[3])
        : "r"(a[0]), "r"(a[1]), "r"(a[2]), "r"(a[3]), "r"(b[0]), "r"(b[1]));
}

__global__ __launch_bounds__(256) void inproj_kernel(const float* __restrict__ U,
                                                     const float* __restrict__ Win) {
    extern __shared__ float smf[];
    const int N = DINPROJ;
    const int K = DMODEL;

    const int tid  = threadIdx.x;
    const int lane = tid & 31;
    const int warp = tid >> 5;
    const int mbase = blockIdx.y * 128;
    const int nbase = blockIdx.x * 64;
    const int mrow0 = (warp & 3) * 32;
    const int ncol0 = (warp >> 2) * 32;

    const int arow = tid >> 1;
    const int acb  = (tid & 1) * 16;
    const int brow = tid >> 2;
    const int bcb  = (tid & 3) * 8;

    float C[2][4][4];
#pragma unroll
    for (int mt = 0; mt < 2; mt++)
#pragma unroll
        for (int nt = 0; nt < 4; nt++)
#pragma unroll
            for (int e = 0; e < 4; e++) C[mt][nt][e] = 0.0f;

    float4 aReg[4];
    float4 bReg[2];

    auto ldg_chunk = [&](int k0) {
#pragma unroll
        for (int q = 0; q < 4; q++)
            aReg[q] = *(const float4*)(U + (mbase + arow) * K + k0 + acb + q * 4);
        if (nbase + brow < N) {
#pragma unroll
            for (int q = 0; q < 2; q++)
                bReg[q] = *(const float4*)(Win + (nbase + brow) * K + k0 + bcb + q * 4);
        } else {
            bReg[0] = make_float4(0.f, 0.f, 0.f, 0.f);
            bReg[1] = make_float4(0.f, 0.f, 0.f, 0.f);
        }
    };

    auto sts_chunk = [&](int buf) {
        float* Ah = smf + IP_AH + buf * 128 * ASTR;
        float* Al = smf + IP_AL + buf * 128 * ASTR;
        float* Bh = smf + IP_BH + buf * 64 * ASTR;
        float* Bl = smf + IP_BL + buf * 64 * ASTR;
#pragma unroll
        for (int q = 0; q < 4; q++) {
            const float* v = (const float*)&aReg[q];
#pragma unroll
            for (int e = 0; e < 4; e++) {
                float x = v[e];
                unsigned hb = tf32_of(x);
                float hf = __uint_as_float(hb);
                unsigned lb = tf32_of(x - hf);
                Ah[arow * ASTR + acb + q * 4 + e] = hf;
                Al[arow * ASTR + acb + q * 4 + e] = __uint_as_float(lb);
            }
        }
#pragma unroll
        for (int q = 0; q < 2; q++) {
            const float* v = (const float*)&bReg[q];
#pragma unroll
            for (int e = 0; e < 4; e++) {
                float x = v[e];
                unsigned hb = tf32_of(x);
                float hf = __uint_as_float(hb);
                unsigned lb = tf32_of(x - hf);
                Bh[brow * ASTR + bcb + q * 4 + e] = hf;
                Bl[brow * ASTR + bcb + q * 4 + e] = __uint_as_float(lb);
            }
        }
    };

    ldg_chunk(0);
    sts_chunk(0);
    __syncthreads();

    const int NCHUNK = K / 32;
    for (int c = 0; c < NCHUNK; c++) {
        int buf = c & 1;
        if (c + 1 < NCHUNK) ldg_chunk((c + 1) * 32);

        const unsigned* Ah = (const unsigned*)(smf + IP_AH + buf * 128 * ASTR);
        const unsigned* Al = (const unsigned*)(smf + IP_AL + buf * 128 * ASTR);
        const unsigned* Bh = (const unsigned*)(smf + IP_BH + buf * 64 * ASTR);
        const unsigned* Bl = (const unsigned*)(smf + IP_BL + buf * 64 * ASTR);

#pragma unroll
        for (int ks = 0; ks < 4; ks++) {
            int kc = ks * 8;
            unsigned ah[2][4], al[2][4], bh[4][2], bl[4][2];
#pragma unroll
            for (int mt = 0; mt < 2; mt++) {
                int r0 = mrow0 + mt * 16 + (lane >> 2);
                int cc = kc + (lane & 3);
                ah[mt][0] = Ah[r0 * ASTR + cc];
                ah[mt][1] = Ah[(r0 + 8) * ASTR + cc];
                ah[mt][2] = Ah[r0 * ASTR + cc + 4];
                ah[mt][3] = Ah[(r0 + 8) * ASTR + cc + 4];
                al[mt][0] = Al[r0 * ASTR + cc];
                al[mt][1] = Al[(r0 + 8) * ASTR + cc];
                al[mt][2] = Al[r0 * ASTR + cc + 4];
                al[mt][3] = Al[(r0 + 8) * ASTR + cc + 4];
            }
#pragma unroll
            for (int nt = 0; nt < 4; nt++) {
                int n0 = ncol0 + nt * 8 + (lane >> 2);
                int kk = kc + (lane & 3);
                bh[nt][0] = Bh[n0 * ASTR + kk];
                bh[nt][1] = Bh[n0 * ASTR + kk + 4];
                bl[nt][0] = Bl[n0 * ASTR + kk];
                bl[nt][1] = Bl[n0 * ASTR + kk + 4];
            }
#pragma unroll
            for (int mt = 0; mt < 2; mt++)
#pragma unroll
                for (int nt = 0; nt < 4; nt++) {
                    mma_tf32(C[mt][nt], ah[mt], bh[nt]);
                    mma_tf32(C[mt][nt], al[mt], bh[nt]);
                    mma_tf32(C[mt][nt], ah[mt], bl[nt]);
                }
        }

        __syncthreads();
        if (c + 1 < NCHUNK) {
            sts_chunk(buf ^ 1);
            __syncthreads();
        }
    }

#pragma unroll
    for (int mt = 0; mt < 2; mt++) {
        int row = mbase + mrow0 + mt * 16 + (lane >> 2);
#pragma unroll
        for (int nt = 0; nt < 4; nt++) {
            int col = nbase + ncol0 + nt * 8 + (lane & 3) * 2;
            if (col < N) {
                g_zxbcdt[row * N + col]           = C[mt][nt][0];
                g_zxbcdt[row * N + col + 1]       = C[mt][nt][1];
                g_zxbcdt[(row + 8) * N + col]     = C[mt][nt][2];
                g_zxbcdt[(row + 8) * N + col + 1] = C[mt][nt][3];
            }
        }
    }
}

// ---------------- kernel 2: causal depthwise conv ----------------
__global__ __launch_bounds__(256) void conv_kernel(const float* __restrict__ conv_w,
                                                   const float* __restrict__ conv_b) {
    int idx = blockIdx.x * blockDim.x + threadIdx.x;
    if (idx >= BATCH * SEQLEN * CONVDIM) return;
    int c  = idx % CONVDIM;
    int bt = idx / CONVDIM;
    int t  = bt % SEQLEN;
    int b  = bt / SEQLEN;
    float accv = conv_b[c];
#pragma unroll
    for (int k = 0; k < DCONV; k++) {
        int tt = t + k - (DCONV - 1);
        if (tt >= 0)
            accv = fmaf(g_zxbcdt[(b * SEQLEN + tt) * DINPROJ + DSSM + c],
                        conv_w[c * DCONV + k], accv);
    }
    g_xbcconv[idx] = accv;
}

// ---------------- kernel 3: persistent scan, depth-2 prefetch + deferred out ----------------
__global__ __launch_bounds__(NTHR, 1) void scan_kernel(
    const float* __restrict__ dt_bias, const float* __restrict__ A_log,
    const float* __restrict__ D_param, const float* __restrict__ norm_w,
    float* __restrict__ out) {

    extern __shared__ float sm[];
    float* s_state = sm + SM_STATE;
    float* s_y     = sm + SM_Y;
    float* s_bc    = sm + SM_BC;
    float* s_red   = sm + SM_RED;
    __shared__ unsigned s_base;

    const int tid  = threadIdx.x;
    const int cta  = blockIdx.x;
    const int lane = tid & 31;
    const int warp = tid >> 5;

    if (tid == 0) s_base = ld_acquire_u(&g_release);
    {
        int i = cta * NTHR + tid;
        if (i < 2 * 128 * 32 * 4) st_rlx_u(&g_yfrag[i], 0u);
    }
    for (int i = tid; i < 256 * 132; i += NTHR) s_state[i] = 0.0f;
    __syncthreads();
    unsigned epoch = s_base + 1;

    const int hasdt = (cta < NHEADS) ? 1 : 0;
    const int ntask = 18 + hasdt + 8;
    const int nact  = 18 + hasdt;           // act-critical rows

    const int p     = tid & 255;
    const int half  = tid >> 8;
    const int h  = cta & 31;
    const int bg = cta >> 5;
    const int b_loc = p >> 6;
    const int dd    = p & 63;
    const int bglb  = bg * 4 + b_loc;
    const float Ah  = -expf(A_log[h]);
    const float dtb = dt_bias[h];
    const float Dh  = D_param[h];
    const float nw  = norm_w[h * HEADDIM + dd];
    const int n0    = half * 64;

    int yk = h * HEADDIM + dd;
    int ys = yk >> 4;
    int yc = yk & 15;
    int yreg = ((yc >= 8) ? 2 : 0) + ((bglb >= 8) ? 1 : 0);
    int yln  = ((bglb & 7) << 2) | ((yc >> 1) & 3);
    int yhalf = yc & 1;
    unsigned short* yb16 = (unsigned short*)g_yfrag;
    int ywi = ((ys * 32 + yln) * 4 + yreg) * 2 + yhalf;

    const int rb = tid >> 3;
    const int rq = tid & 7;

    barrier_arrive(cta, epoch);
    unsigned ewait = epoch;

    for (int t = 0; t <= SEQLEN; t++) {
        // =================== phase A: depth-2 pipelined MMA ===========
        uint4 wb[2][4];
        F4U yhb[2], ylb[2];
        auto load_w = [&](int buf, int sl) {
            int s = (warp << 3) + sl;
            const uint4* wph = (const uint4*)(g_wfrag + ((size_t)(cta * 128 + s) * 2) * 256 + lane * 8);
            const uint4* wpl = (const uint4*)(g_wfrag + ((size_t)(cta * 128 + s) * 2 + 1) * 256 + lane * 8);
            wb[buf][0] = wph[0];
            wb[buf][1] = wph[1];
            wb[buf][2] = wpl[0];
            wb[buf][3] = wpl[1];
        };
        auto load_y = [&](int buf, int sl) {
            int s = (warp << 3) + sl;
            yhb[buf].f = __ldcg((const float4*)(g_yfrag + (s * 32 + lane) * 4));
            ylb[buf].f = __ldcg((const float4*)(g_yfrag + 16384 + (s * 32 + lane) * 4));
        };

        // pre-wait: both W buffers prefetched (read-only)
        load_w(0, 0);
        load_w(1, 1);
        barrier_wait(ewait);
        load_y(0, 0);
        load_y(1, 1);

        float acc[4][4];
#pragma unroll
        for (int nt = 0; nt < 4; nt++)
#pragma unroll
            for (int e = 0; e < 4; e++) acc[nt][e] = 0.0f;

#pragma unroll
        for (int sl = 0; sl < 8; sl++) {
            int cb = sl & 1;

            mma_bf16(acc[0], yhb[cb].v, wb[cb][0].x, wb[cb][0].y);
            mma_bf16(acc[0], ylb[cb].v, wb[cb][0].x, wb[cb][0].y);
            mma_bf16(acc[0], yhb[cb].v, wb[cb][2].x, wb[cb][2].y);

            mma_bf16(acc[1], yhb[cb].v, wb[cb][0].z, wb[cb][0].w);
            mma_bf16(acc[1], ylb[cb].v, wb[cb][0].z, wb[cb][0].w);
            mma_bf16(acc[1], yhb[cb].v, wb[cb][2].z, wb[cb][2].w);

            mma_bf16(acc[2], yhb[cb].v, wb[cb][1].x, wb[cb][1].y);
            mma_bf16(acc[2], ylb[cb].v, wb[cb][1].x, wb[cb][1].y);
            mma_bf16(acc[2], yhb[cb].v, wb[cb][3].x, wb[cb][3].y);

            mma_bf16(acc[3], yhb[cb].v, wb[cb][1].z, wb[cb][1].w);
            mma_bf16(acc[3], ylb[cb].v, wb[cb][1].z, wb[cb][1].w);
            mma_bf16(acc[3], yhb[cb].v, wb[cb][3].z, wb[cb][3].w);

            if (sl < 6) {                    // reload just-consumed buffer for sl+2
                load_w(cb, sl + 2);
                load_y(cb, sl + 2);
            }
        }

        {
            int bq = lane >> 2;
            int c2 = (lane & 3) * 2;
            float* wp = s_y + warp * 512;
#pragma unroll
            for (int nt = 0; nt < 4; nt++) {
                *(float2*)(wp + bq * 32 + nt * 8 + c2)       = make_float2(acc[nt][0], acc[nt][1]);
                *(float2*)(wp + (bq + 8) * 32 + nt * 8 + c2) = make_float2(acc[nt][2], acc[nt][3]);
            }
        }
        // rsqrt factors — hidden in store window
        if (tid < 128) {
            float4 v = __ldcg((const float4*)(g_mspart + rb * 32 + rq * 4));
            float s = (v.x + v.y) + (v.z + v.w);
            s += __shfl_xor_sync(0xffffffffu, s, 1);
            s += __shfl_xor_sync(0xffffffffu, s, 2);
            s += __shfl_xor_sync(0xffffffffu, s, 4);
            if (rq == 0) s_red[rb] = rsqrtf(s * (1.0f / (float)DSSM) + EPSV);
        }
        __syncthreads();

        const int gb = tid >> 5;       // batch
        const int gr = tid & 31;       // row
        // --- act-critical reduction + store, then arrive immediately ---
        if (t < SEQLEN) {
            if (gr < nact) {
                float sum = 0.0f;
#pragma unroll
                for (int w = 0; w < 16; w++) sum += s_y[w * 512 + tid];
                float val = sum * s_red[gb];
                if (gr < 18) {
                    int idxv = cta * 18 + gr;
                    float base = g_xbcconv[(gb * SEQLEN + t) * CONVDIM + idxv];
                    st_rlx_f(&g_act[gb * ACTDIM + idxv], silu_f(base + val));
                } else {
                    float base = g_zxbcdt[(gb * SEQLEN + t) * DINPROJ + (DSSM + CONVDIM) + cta];
                    st_rlx_f(&g_act[gb * ACTDIM + CONVDIM + cta], silu_f(base + val));
                }
            }
            epoch++;
            barrier_arrive(cta, epoch);   // act(t) published (s_y intact past bar)
        }

        // --- deferred out-row reduction (fills the arrive->wait bubble) ---
        if (t >= 1 && gr >= nact && gr < ntask) {
            float sum = 0.0f;
#pragma unroll
            for (int w = 0; w < 16; w++) sum += s_y[w * 512 + tid];
            float val = sum * s_red[gb];
            int idxv = cta * 8 + (gr - nact);
            out[(gb * SEQLEN + (t - 1)) * DMODEL + idxv] = val;
        }

        if (t == SEQLEN) break;

        // pre-wait read-only: z load
        float z = g_zxbcdt[(bglb * SEQLEN + t) * DINPROJ + h * HEADDIM + dd];
        barrier_wait(epoch);          // act(t) visible

        // =================== phase B ===================
        float x   = __ldcg(&g_act[bglb * ACTDIM + h * HEADDIM + dd]);
        float dtr = __ldcg(&g_act[bglb * ACTDIM + CONVDIM + h]);

        {
            int i = tid * 2;
            int bl = i >> 8, k = i & 255;
            float2 v = __ldcg((const float2*)&g_act[(bg * 4 + bl) * ACTDIM + DSSM + k]);
            *(float2*)(s_bc + i) = v;
        }
        __syncthreads();

        float g;
        {
            float dt_v = softplus_f(dtr + dtb);
            float dA  = expf(dt_v * Ah);
            float coef = dt_v * x;

            unsigned long long dA2 = pk2(dA, dA);
            unsigned long long cf2 = pk2(coef, coef);
            unsigned long long acc2 = 0ULL;

            const float* bvp = s_bc + b_loc * 256 + n0;
            const float* cvp = s_bc + b_loc * 256 + 128 + n0;
            float* sp = s_state + p * 132 + n0;
#pragma unroll 4
            for (int n = 0; n < 64; n += 4) {
                F4U sv, bv, cv;
                sv.f = *(float4*)(sp + n);
                bv.f = *(const float4*)(bvp + n);
                cv.f = *(const float4*)(cvp + n);
                sv.u[0] = fma2(sv.u[0], dA2, mul2(cf2, bv.u[0]));
                sv.u[1] = fma2(sv.u[1], dA2, mul2(cf2, bv.u[1]));
                acc2 = fma2(sv.u[0], cv.u[0], acc2);
                acc2 = fma2(sv.u[1], cv.u[1], acc2);
                *(float4*)(sp + n) = sv.f;
            }
            float alo, ahi;
            upk2(acc2, alo, ahi);
            s_y[tid] = alo + ahi;
        }
        __syncthreads();

        if (half == 0) {
            float accv = s_y[tid] + s_y[tid + 256];
            float y = fmaf(Dh, x, accv);
            g = y * silu_f(z);

            float yv = g * nw;
            __nv_bfloat16 hb = __float2bfloat16(yv);
            float hf = __bfloat162float(hb);
            __nv_bfloat16 lb = __float2bfloat16(yv - hf);
            st_rlx_b16(yb16 + ywi, __bfloat16_as_ushort(hb));
            st_rlx_b16(yb16 + 32768 + ywi, __bfloat16_as_ushort(lb));

            float gsq = g * g;
#pragma unroll
            for (int off = 16; off > 0; off >>= 1)
                gsq += __shfl_xor_sync(0xffffffffu, gsq, off);
            if (lane == 0) s_red[16 + warp] = gsq;
        }
        __syncthreads();

        if (tid < 4) {
            float part = s_red[16 + 2 * tid] + s_red[16 + 2 * tid + 1];
            st_rlx_f(&g_mspart[(bg * 4 + tid) * 32 + h], part);
        }

        epoch++;
        barrier_arrive(cta, epoch);   // yfrag(t) + partials published
        ewait = epoch;
    }
}

// ---------------- launcher ----------------
extern "C" void kernel_launch(void* const* d_in, const int* in_sizes, int n_in,
                              void* d_out, int out_size) {
    const float* u       = (const float*)d_in[0];
    const float* W_in    = (const float*)d_in[1];
    const float* conv_w  = (const float*)d_in[2];
    const float* conv_b  = (const float*)d_in[3];
    const float* W_rxbc  = (const float*)d_in[4];
    const float* W_rdt   = (const float*)d_in[5];
    const float* dt_bias = (const float*)d_in[6];
    const float* A_log   = (const float*)d_in[7];
    const float* D_param = (const float*)d_in[8];
    const float* norm_w  = (const float*)d_in[9];
    const float* W_out   = (const float*)d_in[10];
    float* out = (float*)d_out;

    static int attr_set = 0;
    const int SCAN_SMEM = SM_TOTALF * 4;
    const int IP_SMEM   = IP_TOTALF * 4;
    if (!attr_set) {
        cudaFuncSetAttribute(scan_kernel, cudaFuncAttributeMaxDynamicSharedMemorySize, SCAN_SMEM);
        cudaFuncSetAttribute(inproj_kernel, cudaFuncAttributeMaxDynamicSharedMemorySize, IP_SMEM);
        attr_set = 1;
    }

    wfrag_kernel<<<8192, 256>>>(W_rxbc, W_rdt, W_out);

    dim3 gIn((DINPROJ + 63) / 64, (BATCH * SEQLEN) / 128);
    inproj_kernel<<<gIn, 256, IP_SMEM>>>(u, W_in);

    int convN = BATCH * SEQLEN * CONVDIM;
    conv_kernel<<<(convN + 255) / 256, 256>>>(conv_w, conv_b);

    scan_kernel<<<NCTA, NTHR, SCAN_SMEM>>>(dt_bias, A_log, D_param, norm_w, out);
}

// round 17
// speedup vs baseline: 1.4952x; 1.0956x over previous
#include <cuda_runtime.h>
#include <cuda_bf16.h>
#include <cuda_fp16.h>
#include <math.h>

// ---------------- problem constants ----------------
#define BATCH     16
#define SEQLEN    512
#define DMODEL    1024
#define DSTATE    128
#define DCONV     4
#define HEADDIM   64
#define DSSM      2048
#define NHEADS    32
#define CONVDIM   2304            // DSSM + 2*DSTATE
#define DINPROJ   4384            // 2*DSSM + 2*DSTATE + NHEADS
#define ACTDIM    2336            // CONVDIM + NHEADS
#define NCTA      128
#define NTHR      512
#define EPSV      1e-5f
#define WSCALE    64.0f
#define WSCALE_INV (1.0f / 64.0f)

// scan SMEM layout (floats)
#define SM_STATE  0                        // 256*132 = 33792 (state[p][n], pad 132)
#define SM_Y      33792                    // 16*512 = 8192 (warp partials / scratch)
#define SM_BC     (33792 + 8192)           // 1024
#define SM_RED    (33792 + 8192 + 1024)    // 32
#define SM_TOTALF (33792 + 8192 + 1024 + 32)

// ---------------- device scratch ----------------
__device__ float g_zxbcdt[BATCH * SEQLEN * DINPROJ];
__device__ float g_xbcconv[BATCH * SEQLEN * CONVDIM];
__device__ float g_act[BATCH * ACTDIM];
__device__ float g_mspart[BATCH * 32];          // per (batch, head) sum of g^2
__device__ unsigned g_arrive[NCTA * 32];        // padded per-CTA epoch flags
__device__ unsigned g_release;                  // epoch base carrier
// W fragments (fp16 single plane, scaled): [cta][s(128)][lane(32)][nt(4)][b0,b1] -> 16.8 MB
__device__ unsigned g_wfrag[128 * 128 * 256];
// Y fragments (fp16 hi/lo): [hilo][s(128)][lane(32)][reg(4)] u32 (half2) -> 128 KB
__device__ unsigned g_yfrag[2 * 128 * 32 * 4];

// ---------------- helpers ----------------
__device__ __forceinline__ float silu_f(float v) { return v / (1.0f + expf(-v)); }
__device__ __forceinline__ float softplus_f(float v) { return (v > 20.0f) ? v : log1pf(expf(v)); }

__device__ __forceinline__ void upk2(unsigned long long v, float& lo, float& hi) {
    unsigned a, b;
    asm("mov.b64 {%0, %1}, %2;" : "=r"(a), "=r"(b) : "l"(v));
    lo = __uint_as_float(a); hi = __uint_as_float(b);
}
__device__ __forceinline__ unsigned long long pk2(float lo, float hi) {
    unsigned long long r;
    asm("mov.b64 %0, {%1, %2};" : "=l"(r) : "r"(__float_as_uint(lo)), "r"(__float_as_uint(hi)));
    return r;
}
__device__ __forceinline__ unsigned long long fma2(unsigned long long a, unsigned long long b,
                                                   unsigned long long c) {
    unsigned long long d;
    asm("fma.rn.f32x2 %0, %1, %2, %3;" : "=l"(d) : "l"(a), "l"(b), "l"(c));
    return d;
}
__device__ __forceinline__ unsigned long long mul2(unsigned long long a, unsigned long long b) {
    unsigned long long d;
    asm("mul.rn.f32x2 %0, %1, %2;" : "=l"(d) : "l"(a), "l"(b));
    return d;
}
__device__ __forceinline__ unsigned tf32_of(float x) {
    unsigned r;
    asm("cvt.rna.tf32.f32 %0, %1;" : "=r"(r) : "f"(x));
    return r;
}

// ---- strong flag ops ----
__device__ __forceinline__ void st_release_u(unsigned* p, unsigned v) {
    asm volatile("st.release.gpu.global.u32 [%0], %1;" :: "l"(p), "r"(v) : "memory");
}
__device__ __forceinline__ unsigned ld_acquire_u(const unsigned* p) {
    unsigned v;
    asm volatile("ld.acquire.gpu.global.u32 %0, [%1];" : "=r"(v) : "l"(p) : "memory");
    return v;
}
// ---- mutable-data stores: volatile relaxed ----
__device__ __forceinline__ void st_rlx_f(float* p, float v) {
    asm volatile("st.relaxed.gpu.global.f32 [%0], %1;" :: "l"(p), "f"(v) : "memory");
}
__device__ __forceinline__ void st_rlx_u(unsigned* p, unsigned v) {
    asm volatile("st.relaxed.gpu.global.u32 [%0], %1;" :: "l"(p), "r"(v) : "memory");
}
__device__ __forceinline__ void st_rlx_b16(unsigned short* p, unsigned short v) {
    asm volatile("st.relaxed.gpu.global.b16 [%0], %1;" :: "l"(p), "h"(v) : "memory");
}

union F4U { float4 f; unsigned long long u[2]; unsigned v[4]; };

// SPLIT-PHASE flat grid barrier (128 CTAs).
__device__ __forceinline__ void barrier_arrive(int cta, unsigned epoch) {
    __syncthreads();
    if (threadIdx.x == 0) st_release_u(&g_arrive[cta * 32], epoch);
}
__device__ __forceinline__ void barrier_wait(unsigned epoch) {
    if (threadIdx.x < 128) {
        while (ld_acquire_u(&g_arrive[threadIdx.x * 32]) < epoch) { }
    }
    __syncthreads();
}

// fp16 MMA (non-volatile)
__device__ __forceinline__ void mma_f16(float* d, const unsigned* a, unsigned b0, unsigned b1) {
    asm("mma.sync.aligned.m16n8k16.row.col.f32.f16.f16.f32 "
        "{%0,%1,%2,%3}, {%4,%5,%6,%7}, {%8,%9}, {%0,%1,%2,%3};"
        : "+f"(d[0]), "+f"(d[1]), "+f"(d[2]), "+f"(d[3])
        : "r"(a[0]), "r"(a[1]), "r"(a[2]), "r"(a[3]), "r"(b0), "r"(b1));
}

// ---------------- kernel 0: precompute W fragments (fp16, scaled) ----------------
__global__ __launch_bounds__(256) void wfrag_kernel(const float* __restrict__ W_rxbc,
                                                    const float* __restrict__ W_rdt,
                                                    const float* __restrict__ W_out) {
    int idx = blockIdx.x * 256 + threadIdx.x;      // < 128*128*32*4
    int nt   = idx & 3;
    int lane = (idx >> 2) & 31;
    int s    = (idx >> 7) & 127;
    int cta  = idx >> 14;
    int hasdt = (cta < NHEADS) ? 1 : 0;
    int ntask = 18 + hasdt + 8;
    int n_local = nt * 8 + (lane >> 2);
    int k0 = s * 16 + (lane & 3) * 2;

    float w00 = 0.f, w01 = 0.f, w10 = 0.f, w11 = 0.f;
    float sc = 1.0f;
    if (n_local < ntask) {
        const float* p;
        if (n_local < 18) { p = W_rxbc + (size_t)(cta * 18 + n_local) * DSSM; sc = WSCALE; }
        else if (hasdt && n_local == 18) { p = W_rdt + (size_t)cta * DSSM; sc = WSCALE; }
        else p = W_out + (size_t)(cta * 8 + n_local - 18 - hasdt) * DSSM;
        w00 = p[k0]; w01 = p[k0 + 1]; w10 = p[k0 + 8]; w11 = p[k0 + 9];
    }

    unsigned short h00 = __half_as_ushort(__float2half_rn(w00 * sc));
    unsigned short h01 = __half_as_ushort(__float2half_rn(w01 * sc));
    unsigned short h10 = __half_as_ushort(__float2half_rn(w10 * sc));
    unsigned short h11 = __half_as_ushort(__float2half_rn(w11 * sc));

    size_t base = (size_t)(cta * 128 + s) * 256 + lane * 8 + nt * 2;
    g_wfrag[base]     = (unsigned)h00 | ((unsigned)h01 << 16);
    g_wfrag[base + 1] = (unsigned)h10 | ((unsigned)h11 << 16);
}

// ---------------- kernel 1: in_proj GEMM, tf32 mma (unchanged) --------
#define ASTR 36
#define IP_AH 0
#define IP_AL (2 * 128 * ASTR)
#define IP_BH (4 * 128 * ASTR)
#define IP_BL (4 * 128 * ASTR + 2 * 64 * ASTR)
#define IP_TOTALF (4 * 128 * ASTR + 4 * 64 * ASTR)

__device__ __forceinline__ void mma_tf32(float* d, const unsigned* a, const unsigned* b) {
    asm volatile(
        "mma.sync.aligned.m16n8k8.row.col.f32.tf32.tf32.f32 "
        "{%0,%1,%2,%3}, {%4,%5,%6,%7}, {%8,%9}, {%0,%1,%2,%3};"
        : "+f"(d[0]), "+f"(d[1]), "+f"(d[2]), "+f"(d[3])
        : "r"(a[0]), "r"(a[1]), "r"(a[2]), "r"(a[3]), "r"(b[0]), "r"(b[1]));
}

__global__ __launch_bounds__(256) void inproj_kernel(const float* __restrict__ U,
                                                     const float* __restrict__ Win) {
    extern __shared__ float smf[];
    const int N = DINPROJ;
    const int K = DMODEL;

    const int tid  = threadIdx.x;
    const int lane = tid & 31;
    const int warp = tid >> 5;
    const int mbase = blockIdx.y * 128;
    const int nbase = blockIdx.x * 64;
    const int mrow0 = (warp & 3) * 32;
    const int ncol0 = (warp >> 2) * 32;

    const int arow = tid >> 1;
    const int acb  = (tid & 1) * 16;
    const int brow = tid >> 2;
    const int bcb  = (tid & 3) * 8;

    float C[2][4][4];
#pragma unroll
    for (int mt = 0; mt < 2; mt++)
#pragma unroll
        for (int nt = 0; nt < 4; nt++)
#pragma unroll
            for (int e = 0; e < 4; e++) C[mt][nt][e] = 0.0f;

    float4 aReg[4];
    float4 bReg[2];

    auto ldg_chunk = [&](int k0) {
#pragma unroll
        for (int q = 0; q < 4; q++)
            aReg[q] = *(const float4*)(U + (mbase + arow) * K + k0 + acb + q * 4);
        if (nbase + brow < N) {
#pragma unroll
            for (int q = 0; q < 2; q++)
                bReg[q] = *(const float4*)(Win + (nbase + brow) * K + k0 + bcb + q * 4);
        } else {
            bReg[0] = make_float4(0.f, 0.f, 0.f, 0.f);
            bReg[1] = make_float4(0.f, 0.f, 0.f, 0.f);
        }
    };

    auto sts_chunk = [&](int buf) {
        float* Ah = smf + IP_AH + buf * 128 * ASTR;
        float* Al = smf + IP_AL + buf * 128 * ASTR;
        float* Bh = smf + IP_BH + buf * 64 * ASTR;
        float* Bl = smf + IP_BL + buf * 64 * ASTR;
#pragma unroll
        for (int q = 0; q < 4; q++) {
            const float* v = (const float*)&aReg[q];
#pragma unroll
            for (int e = 0; e < 4; e++) {
                float x = v[e];
                unsigned hb = tf32_of(x);
                float hf = __uint_as_float(hb);
                unsigned lb = tf32_of(x - hf);
                Ah[arow * ASTR + acb + q * 4 + e] = hf;
                Al[arow * ASTR + acb + q * 4 + e] = __uint_as_float(lb);
            }
        }
#pragma unroll
        for (int q = 0; q < 2; q++) {
            const float* v = (const float*)&bReg[q];
#pragma unroll
            for (int e = 0; e < 4; e++) {
                float x = v[e];
                unsigned hb = tf32_of(x);
                float hf = __uint_as_float(hb);
                unsigned lb = tf32_of(x - hf);
                Bh[brow * ASTR + bcb + q * 4 + e] = hf;
                Bl[brow * ASTR + bcb + q * 4 + e] = __uint_as_float(lb);
            }
        }
    };

    ldg_chunk(0);
    sts_chunk(0);
    __syncthreads();

    const int NCHUNK = K / 32;
    for (int c = 0; c < NCHUNK; c++) {
        int buf = c & 1;
        if (c + 1 < NCHUNK) ldg_chunk((c + 1) * 32);

        const unsigned* Ah = (const unsigned*)(smf + IP_AH + buf * 128 * ASTR);
        const unsigned* Al = (const unsigned*)(smf + IP_AL + buf * 128 * ASTR);
        const unsigned* Bh = (const unsigned*)(smf + IP_BH + buf * 64 * ASTR);
        const unsigned* Bl = (const unsigned*)(smf + IP_BL + buf * 64 * ASTR);

#pragma unroll
        for (int ks = 0; ks < 4; ks++) {
            int kc = ks * 8;
            unsigned ah[2][4], al[2][4], bh[4][2], bl[4][2];
#pragma unroll
            for (int mt = 0; mt < 2; mt++) {
                int r0 = mrow0 + mt * 16 + (lane >> 2);
                int cc = kc + (lane & 3);
                ah[mt][0] = Ah[r0 * ASTR + cc];
                ah[mt][1] = Ah[(r0 + 8) * ASTR + cc];
                ah[mt][2] = Ah[r0 * ASTR + cc + 4];
                ah[mt][3] = Ah[(r0 + 8) * ASTR + cc + 4];
                al[mt][0] = Al[r0 * ASTR + cc];
                al[mt][1] = Al[(r0 + 8) * ASTR + cc];
                al[mt][2] = Al[r0 * ASTR + cc + 4];
                al[mt][3] = Al[(r0 + 8) * ASTR + cc + 4];
            }
#pragma unroll
            for (int nt = 0; nt < 4; nt++) {
                int n0 = ncol0 + nt * 8 + (lane >> 2);
                int kk = kc + (lane & 3);
                bh[nt][0] = Bh[n0 * ASTR + kk];
                bh[nt][1] = Bh[n0 * ASTR + kk + 4];
                bl[nt][0] = Bl[n0 * ASTR + kk];
                bl[nt][1] = Bl[n0 * ASTR + kk + 4];
            }
#pragma unroll
            for (int mt = 0; mt < 2; mt++)
#pragma unroll
                for (int nt = 0; nt < 4; nt++) {
                    mma_tf32(C[mt][nt], ah[mt], bh[nt]);
                    mma_tf32(C[mt][nt], al[mt], bh[nt]);
                    mma_tf32(C[mt][nt], ah[mt], bl[nt]);
                }
        }

        __syncthreads();
        if (c + 1 < NCHUNK) {
            sts_chunk(buf ^ 1);
            __syncthreads();
        }
    }

#pragma unroll
    for (int mt = 0; mt < 2; mt++) {
        int row = mbase + mrow0 + mt * 16 + (lane >> 2);
#pragma unroll
        for (int nt = 0; nt < 4; nt++) {
            int col = nbase + ncol0 + nt * 8 + (lane & 3) * 2;
            if (col < N) {
                g_zxbcdt[row * N + col]           = C[mt][nt][0];
                g_zxbcdt[row * N + col + 1]       = C[mt][nt][1];
                g_zxbcdt[(row + 8) * N + col]     = C[mt][nt][2];
                g_zxbcdt[(row + 8) * N + col + 1] = C[mt][nt][3];
            }
        }
    }
}

// ---------------- kernel 2: causal depthwise conv ----------------
__global__ __launch_bounds__(256) void conv_kernel(const float* __restrict__ conv_w,
                                                   const float* __restrict__ conv_b) {
    int idx = blockIdx.x * blockDim.x + threadIdx.x;
    if (idx >= BATCH * SEQLEN * CONVDIM) return;
    int c  = idx % CONVDIM;
    int bt = idx / CONVDIM;
    int t  = bt % SEQLEN;
    int b  = bt / SEQLEN;
    float accv = conv_b[c];
#pragma unroll
    for (int k = 0; k < DCONV; k++) {
        int tt = t + k - (DCONV - 1);
        if (tt >= 0)
            accv = fmaf(g_zxbcdt[(b * SEQLEN + tt) * DINPROJ + DSSM + c],
                        conv_w[c * DCONV + k], accv);
    }
    g_xbcconv[idx] = accv;
}

// ---------------- kernel 3: persistent scan, fp16-W depth-2 pipeline ----------------
__global__ __launch_bounds__(NTHR, 1) void scan_kernel(
    const float* __restrict__ dt_bias, const float* __restrict__ A_log,
    const float* __restrict__ D_param, const float* __restrict__ norm_w,
    float* __restrict__ out) {

    extern __shared__ float sm[];
    float* s_state = sm + SM_STATE;
    float* s_y     = sm + SM_Y;
    float* s_bc    = sm + SM_BC;
    float* s_red   = sm + SM_RED;
    __shared__ unsigned s_base;

    const int tid  = threadIdx.x;
    const int cta  = blockIdx.x;
    const int lane = tid & 31;
    const int warp = tid >> 5;

    if (tid == 0) s_base = ld_acquire_u(&g_release);
    {
        int i = cta * NTHR + tid;
        if (i < 2 * 128 * 32 * 4) st_rlx_u(&g_yfrag[i], 0u);
    }
    for (int i = tid; i < 256 * 132; i += NTHR) s_state[i] = 0.0f;
    __syncthreads();
    unsigned epoch = s_base + 1;

    const int hasdt = (cta < NHEADS) ? 1 : 0;
    const int ntask = 18 + hasdt + 8;
    const int nact  = 18 + hasdt;

    const int p     = tid & 255;
    const int half  = tid >> 8;
    const int h  = cta & 31;
    const int bg = cta >> 5;
    const int b_loc = p >> 6;
    const int dd    = p & 63;
    const int bglb  = bg * 4 + b_loc;
    const float Ah  = -expf(A_log[h]);
    const float dtb = dt_bias[h];
    const float Dh  = D_param[h];
    const float nw  = norm_w[h * HEADDIM + dd];
    const int n0    = half * 64;

    int yk = h * HEADDIM + dd;
    int ys = yk >> 4;
    int yc = yk & 15;
    int yreg = ((yc >= 8) ? 2 : 0) + ((bglb >= 8) ? 1 : 0);
    int yln  = ((bglb & 7) << 2) | ((yc >> 1) & 3);
    int yhalf = yc & 1;
    unsigned short* yb16 = (unsigned short*)g_yfrag;
    int ywi = ((ys * 32 + yln) * 4 + yreg) * 2 + yhalf;

    const int rb = tid >> 3;
    const int rq = tid & 7;

    barrier_arrive(cta, epoch);
    unsigned ewait = epoch;

    for (int t = 0; t <= SEQLEN; t++) {
        // =================== phase A: depth-2 pipelined fp16 MMA ===========
        uint4 wb[2][2];
        F4U yhb[2], ylb[2];
        auto load_w = [&](int buf, int sl) {
            int s = (warp << 3) + sl;
            const uint4* wp = (const uint4*)(g_wfrag + (size_t)(cta * 128 + s) * 256 + lane * 8);
            wb[buf][0] = wp[0];
            wb[buf][1] = wp[1];
        };
        auto load_y = [&](int buf, int sl) {
            int s = (warp << 3) + sl;
            yhb[buf].f = __ldcg((const float4*)(g_yfrag + (s * 32 + lane) * 4));
            ylb[buf].f = __ldcg((const float4*)(g_yfrag + 16384 + (s * 32 + lane) * 4));
        };

        load_w(0, 0);
        load_w(1, 1);
        barrier_wait(ewait);
        load_y(0, 0);
        load_y(1, 1);

        float acc[4][4];
#pragma unroll
        for (int nt = 0; nt < 4; nt++)
#pragma unroll
            for (int e = 0; e < 4; e++) acc[nt][e] = 0.0f;

#pragma unroll
        for (int sl = 0; sl < 8; sl++) {
            int cb = sl & 1;

            mma_f16(acc[0], yhb[cb].v, wb[cb][0].x, wb[cb][0].y);
            mma_f16(acc[0], ylb[cb].v, wb[cb][0].x, wb[cb][0].y);

            mma_f16(acc[1], yhb[cb].v, wb[cb][0].z, wb[cb][0].w);
            mma_f16(acc[1], ylb[cb].v, wb[cb][0].z, wb[cb][0].w);

            mma_f16(acc[2], yhb[cb].v, wb[cb][1].x, wb[cb][1].y);
            mma_f16(acc[2], ylb[cb].v, wb[cb][1].x, wb[cb][1].y);

            mma_f16(acc[3], yhb[cb].v, wb[cb][1].z, wb[cb][1].w);
            mma_f16(acc[3], ylb[cb].v, wb[cb][1].z, wb[cb][1].w);

            if (sl < 6) {
                load_w(cb, sl + 2);
                load_y(cb, sl + 2);
            }
        }

        {
            int bq = lane >> 2;
            int c2 = (lane & 3) * 2;
            float* wp = s_y + warp * 512;
#pragma unroll
            for (int nt = 0; nt < 4; nt++) {
                *(float2*)(wp + bq * 32 + nt * 8 + c2)       = make_float2(acc[nt][0], acc[nt][1]);
                *(float2*)(wp + (bq + 8) * 32 + nt * 8 + c2) = make_float2(acc[nt][2], acc[nt][3]);
            }
        }
        if (tid < 128) {
            float4 v = __ldcg((const float4*)(g_mspart + rb * 32 + rq * 4));
            float s = (v.x + v.y) + (v.z + v.w);
            s += __shfl_xor_sync(0xffffffffu, s, 1);
            s += __shfl_xor_sync(0xffffffffu, s, 2);
            s += __shfl_xor_sync(0xffffffffu, s, 4);
            if (rq == 0) s_red[rb] = rsqrtf(s * (1.0f / (float)DSSM) + EPSV);
        }
        __syncthreads();

        const int gb = tid >> 5;
        const int gr = tid & 31;
        // --- act-critical reduction + store, then arrive ---
        if (t < SEQLEN) {
            if (gr < nact) {
                float sum = 0.0f;
#pragma unroll
                for (int w = 0; w < 16; w++) sum += s_y[w * 512 + tid];
                float val = sum * s_red[gb] * WSCALE_INV;   // un-scale rxbc/dt rows
                if (gr < 18) {
                    int idxv = cta * 18 + gr;
                    float base = g_xbcconv[(gb * SEQLEN + t) * CONVDIM + idxv];
                    st_rlx_f(&g_act[gb * ACTDIM + idxv], silu_f(base + val));
                } else {
                    float base = g_zxbcdt[(gb * SEQLEN + t) * DINPROJ + (DSSM + CONVDIM) + cta];
                    st_rlx_f(&g_act[gb * ACTDIM + CONVDIM + cta], silu_f(base + val));
                }
            }
            epoch++;
            barrier_arrive(cta, epoch);
        }

        // --- deferred out-row reduction (unscaled W rows) ---
        if (t >= 1 && gr >= nact && gr < ntask) {
            float sum = 0.0f;
#pragma unroll
            for (int w = 0; w < 16; w++) sum += s_y[w * 512 + tid];
            float val = sum * s_red[gb];
            int idxv = cta * 8 + (gr - nact);
            out[(gb * SEQLEN + (t - 1)) * DMODEL + idxv] = val;
        }

        if (t == SEQLEN) break;

        float z = g_zxbcdt[(bglb * SEQLEN + t) * DINPROJ + h * HEADDIM + dd];
        barrier_wait(epoch);

        // =================== phase B ===================
        float x   = __ldcg(&g_act[bglb * ACTDIM + h * HEADDIM + dd]);
        float dtr = __ldcg(&g_act[bglb * ACTDIM + CONVDIM + h]);

        {
            int i = tid * 2;
            int bl = i >> 8, k = i & 255;
            float2 v = __ldcg((const float2*)&g_act[(bg * 4 + bl) * ACTDIM + DSSM + k]);
            *(float2*)(s_bc + i) = v;
        }
        __syncthreads();

        float g;
        {
            float dt_v = softplus_f(dtr + dtb);
            float dA  = expf(dt_v * Ah);
            float coef = dt_v * x;

            unsigned long long dA2 = pk2(dA, dA);
            unsigned long long cf2 = pk2(coef, coef);
            unsigned long long acc2 = 0ULL;

            const float* bvp = s_bc + b_loc * 256 + n0;
            const float* cvp = s_bc + b_loc * 256 + 128 + n0;
            float* sp = s_state + p * 132 + n0;
#pragma unroll 4
            for (int n = 0; n < 64; n += 4) {
                F4U sv, bv, cv;
                sv.f = *(float4*)(sp + n);
                bv.f = *(const float4*)(bvp + n);
                cv.f = *(const float4*)(cvp + n);
                sv.u[0] = fma2(sv.u[0], dA2, mul2(cf2, bv.u[0]));
                sv.u[1] = fma2(sv.u[1], dA2, mul2(cf2, bv.u[1]));
                acc2 = fma2(sv.u[0], cv.u[0], acc2);
                acc2 = fma2(sv.u[1], cv.u[1], acc2);
                *(float4*)(sp + n) = sv.f;
            }
            float alo, ahi;
            upk2(acc2, alo, ahi);
            s_y[tid] = alo + ahi;
        }
        __syncthreads();

        if (half == 0) {
            float accv = s_y[tid] + s_y[tid + 256];
            float y = fmaf(Dh, x, accv);
            g = y * silu_f(z);

            // write Y fragment (fp16 hi/lo)
            float yv = g * nw;
            __half hb = __float2half_rn(yv);
            float hf = __half2float(hb);
            __half lb = __float2half_rn(yv - hf);
            st_rlx_b16(yb16 + ywi, __half_as_ushort(hb));
            st_rlx_b16(yb16 + 32768 + ywi, __half_as_ushort(lb));

            float gsq = g * g;
#pragma unroll
            for (int off = 16; off > 0; off >>= 1)
                gsq += __shfl_xor_sync(0xffffffffu, gsq, off);
            if (lane == 0) s_red[16 + warp] = gsq;
        }
        __syncthreads();

        if (tid < 4) {
            float part = s_red[16 + 2 * tid] + s_red[16 + 2 * tid + 1];
            st_rlx_f(&g_mspart[(bg * 4 + tid) * 32 + h], part);
        }

        epoch++;
        barrier_arrive(cta, epoch);
        ewait = epoch;
    }
}

// ---------------- launcher ----------------
extern "C" void kernel_launch(void* const* d_in, const int* in_sizes, int n_in,
                              void* d_out, int out_size) {
    const float* u       = (const float*)d_in[0];
    const float* W_in    = (const float*)d_in[1];
    const float* conv_w  = (const float*)d_in[2];
    const float* conv_b  = (const float*)d_in[3];
    const float* W_rxbc  = (const float*)d_in[4];
    const float* W_rdt   = (const float*)d_in[5];
    const float* dt_bias = (const float*)d_in[6];
    const float* A_log   = (const float*)d_in[7];
    const float* D_param = (const float*)d_in[8];
    const float* norm_w  = (const float*)d_in[9];
    const float* W_out   = (const float*)d_in[10];
    float* out = (float*)d_out;

    static int attr_set = 0;
    const int SCAN_SMEM = SM_TOTALF * 4;
    const int IP_SMEM   = IP_TOTALF * 4;
    if (!attr_set) {
        cudaFuncSetAttribute(scan_kernel, cudaFuncAttributeMaxDynamicSharedMemorySize, SCAN_SMEM);
        cudaFuncSetAttribute(inproj_kernel, cudaFuncAttributeMaxDynamicSharedMemorySize, IP_SMEM);
        attr_set = 1;
    }

    wfrag_kernel<<<8192, 256>>>(W_rxbc, W_rdt, W_out);

    dim3 gIn((DINPROJ + 63) / 64, (BATCH * SEQLEN) / 128);
    inproj_kernel<<<gIn, 256, IP_SMEM>>>(u, W_in);

    int convN = BATCH * SEQLEN * CONVDIM;
    conv_kernel<<<(convN + 255) / 256, 256>>>(conv_w, conv_b);

    scan_kernel<<<NCTA, NTHR, SCAN_SMEM>>>(dt_bias, A_log, D_param, norm_w, out);
}